// round 8
// baseline (speedup 1.0000x reference)
#include <cuda_runtime.h>
#include <cstdint>

#define HEADS 32
#define S_LEN 2048
#define DIM   128
#define LOCAL 16

#define KSTR 144   // smem words per K row (packed), 144%32==16 -> conflict-free LDS.128
#define VSTR 132   // smem words per V row (permuted), 132%16==4
#define SMEM_FLOATS (64*KSTR + 64*VSTR)   // 70656 bytes

// precomputed per-(head,token) rows, tile-ready
__device__ unsigned g_Kpack[(size_t)HEADS * S_LEN * DIM];   // 32 MB
__device__ unsigned g_Vperm[(size_t)HEADS * S_LEN * DIM];   // 32 MB

__device__ __forceinline__ unsigned f2tf32(float x) {
    unsigned r; asm("cvt.rna.tf32.f32 %0, %1;" : "=r"(r) : "f"(x)); return r;
}
__device__ __forceinline__ unsigned pack_bf16x2(float lo_el, float hi_el) {
    unsigned r; asm("cvt.rn.bf16x2.f32 %0, %1, %2;" : "=r"(r) : "f"(hi_el), "f"(lo_el)); return r;
}
__device__ __forceinline__ float bf2f_lo(unsigned w) { return __uint_as_float(w << 16); }
__device__ __forceinline__ float bf2f_hi(unsigned w) { return __uint_as_float(w & 0xFFFF0000u); }
__device__ __forceinline__ void split2(float x0, float x1, unsigned& wh, unsigned& wl) {
    wh = pack_bf16x2(x0, x1);
    wl = pack_bf16x2(x0 - bf2f_lo(wh), x1 - bf2f_hi(wh));
}
__device__ __forceinline__ void mma_bf16(float c[4],
                                         unsigned a0, unsigned a1, unsigned a2, unsigned a3,
                                         unsigned b0, unsigned b1) {
    asm volatile(
        "mma.sync.aligned.m16n8k16.row.col.f32.bf16.bf16.f32 "
        "{%0,%1,%2,%3}, {%4,%5,%6,%7}, {%8,%9}, {%0,%1,%2,%3};"
        : "+f"(c[0]), "+f"(c[1]), "+f"(c[2]), "+f"(c[3])
        : "r"(a0), "r"(a1), "r"(a2), "r"(a3), "r"(b0), "r"(b1));
}
__device__ __forceinline__ void mma_tf32(float c[4],
                                         unsigned a0, unsigned a1, unsigned a2, unsigned a3,
                                         unsigned b0, unsigned b1) {
    asm volatile(
        "mma.sync.aligned.m16n8k8.row.col.f32.tf32.tf32.f32 "
        "{%0,%1,%2,%3}, {%4,%5,%6,%7}, {%8,%9}, {%0,%1,%2,%3};"
        : "+f"(c[0]), "+f"(c[1]), "+f"(c[2]), "+f"(c[3])
        : "r"(a0), "r"(a1), "r"(a2), "r"(a3), "r"(b0), "r"(b1));
}
__device__ __forceinline__ uint32_t smem_u32(const void* p) {
    uint32_t a;
    asm("{ .reg .u64 t; cvta.to.shared.u64 t, %1; cvt.u32.u64 %0, t; }" : "=r"(a) : "l"(p));
    return a;
}
__device__ __forceinline__ void cp16(uint32_t dst, const void* src) {
    asm volatile("cp.async.ca.shared.global [%0], [%1], 16;" :: "r"(dst), "l"(src));
}

// ---- prepass: K -> bf16 hi/lo packed; V -> tf32 permuted ----
__global__ __launch_bounds__(256)
void prepack_kernel(const float* __restrict__ K, const float* __restrict__ V) {
    const int gid = blockIdx.x * 256 + threadIdx.x;   // 2M jobs: (row, j)
    const int rid = gid >> 5;        // 0..65535 = h*2048 + s
    const int j   = gid & 31;
    const int h   = rid >> 11;
    const int s   = rid & 2047;
    const size_t src_row = ((size_t)s * HEADS + h) * DIM;
    const size_t dst_row = (size_t)rid * DIM;

    // K: elementwise word-group transform (content group of dims 4j lands at word 4j)
    const float4 k4 = __ldg((const float4*)(K + src_row) + j);
    unsigned h1, l1, h2, l2;
    split2(k4.x, k4.y, h1, l1);
    split2(k4.z, k4.w, h2, l2);
    *(uint4*)&g_Kpack[dst_row + j * 4] = make_uint4(h1, l1, h2, l2);

    // V: permuted p = (d&7)*16 + (d>>3); thread writes words 4j..4j+3 (coalesced),
    // gathers the 4 source dims d = ((p&15)<<3) | (p>>4)
    unsigned vw[4];
    #pragma unroll
    for (int m = 0; m < 4; ++m) {
        const int p = 4 * j + m;
        const int d = ((p & 15) << 3) | (p >> 4);
        vw[m] = f2tf32(__ldg(V + src_row + d));
    }
    *(uint4*)&g_Vperm[dst_row + j * 4] = make_uint4(vw[0], vw[1], vw[2], vw[3]);
}

__global__ __launch_bounds__(128, 2)
void sparse_attn_cp_kernel(const float* __restrict__ Q,
                           float* __restrict__ O) {
    extern __shared__ float sm[];
    float* Kc = sm;                 // [64][KSTR]
    float* Vp = sm + 64 * KSTR;     // [64][VSTR]
    unsigned* Ku = (unsigned*)Kc;
    const uint32_t sbK = smem_u32(Kc);
    const uint32_t sbV = smem_u32(Vp);

    const int qb   = blockIdx.x;
    const int h    = blockIdx.y;
    const int t    = threadIdx.x;   // 0..127
    const int w    = t >> 5;
    const int lane = t & 31;
    const int lr   = lane >> 2;
    const int lc   = lane & 3;

    const int s0  = qb * 64 + w * 16 + lr;
    const int s1  = s0 + 8;
    const float scale = 0.08838834764831845f;

    // ---- Q fragments in registers (scaled, split hi/lo) ----
    unsigned qa0[8][4], qa1[8][4];
    {
        const float* Qp0 = Q + ((size_t)s0 * HEADS + h) * DIM;
        const float* Qp1 = Q + ((size_t)s1 * HEADS + h) * DIM;
        #pragma unroll
        for (int kg = 0; kg < 8; ++kg) {
            const float4 A = *(const float4*)(Qp0 + kg * 16 + lc * 4);
            const float4 B = *(const float4*)(Qp1 + kg * 16 + lc * 4);
            split2(A.x * scale, A.y * scale, qa0[kg][0], qa0[kg][1]);
            split2(A.z * scale, A.w * scale, qa0[kg][2], qa0[kg][3]);
            split2(B.x * scale, B.y * scale, qa1[kg][0], qa1[kg][1]);
            split2(B.z * scale, B.w * scale, qa1[kg][2], qa1[kg][3]);
        }
    }

    float oacc[16][4];
    #pragma unroll
    for (int nt = 0; nt < 16; ++nt)
        #pragma unroll
        for (int j = 0; j < 4; ++j) oacc[nt][j] = 0.0f;
    float ls0 = 0.0f, ls1 = 0.0f;

    const size_t hbase = (size_t)h * S_LEN * DIM;

    for (int kb = 0; kb <= qb; ++kb) {
        const bool vert = ((kb + h + 1) & 7) == 0;
        if (!(((qb - kb) < LOCAL) || vert)) continue;

        __syncthreads();   // prior compute done; Kc/Vp free

        // ---- loader: pure cp.async from precomputed buffers ----
        const unsigned* gK = g_Kpack + hbase + (size_t)kb * 64 * DIM;
        const unsigned* gV = g_Vperm + hbase + (size_t)kb * 64 * DIM;
        #pragma unroll
        for (int it = 0; it < 16; ++it) {
            const int idx = t + it * 128;     // 0..2047
            const int r = idx >> 5, c = idx & 31;
            cp16(sbK + (r * KSTR + c * 4) * 4, gK + r * DIM + c * 4);
            cp16(sbV + (r * VSTR + c * 4) * 4, gV + r * DIM + c * 4);
        }
        asm volatile("cp.async.commit_group;" ::: "memory");
        asm volatile("cp.async.wait_group 0;" ::: "memory");
        __syncthreads();

        // ---- S = Q K^T : 3-term bf16 split ----
        float sf[8][4];
        #pragma unroll
        for (int nt = 0; nt < 8; ++nt)
            #pragma unroll
            for (int j = 0; j < 4; ++j) sf[nt][j] = 0.0f;

        #pragma unroll
        for (int kg = 0; kg < 8; ++kg) {
            #pragma unroll
            for (int nt = 0; nt < 8; ++nt) {
                const uint4 B = *(const uint4*)&Ku[(nt * 8 + lr) * KSTR + kg * 16 + lc * 4];
                mma_bf16(sf[nt], qa0[kg][0], qa1[kg][0], qa0[kg][2], qa1[kg][2], B.x, B.z);
                mma_bf16(sf[nt], qa0[kg][0], qa1[kg][0], qa0[kg][2], qa1[kg][2], B.y, B.w);
                mma_bf16(sf[nt], qa0[kg][1], qa1[kg][1], qa0[kg][3], qa1[kg][3], B.x, B.z);
            }
        }

        // ---- softmax in registers (fixed-max; shift-invariant) ----
        if (kb == qb) {
            #pragma unroll
            for (int nt = 0; nt < 8; ++nt) {
                const int c0 = kb * 64 + nt * 8 + lc * 2;
                sf[nt][0] = (c0     <= s0) ? __expf(sf[nt][0]) : 0.0f;
                sf[nt][1] = (c0 + 1 <= s0) ? __expf(sf[nt][1]) : 0.0f;
                sf[nt][2] = (c0     <= s1) ? __expf(sf[nt][2]) : 0.0f;
                sf[nt][3] = (c0 + 1 <= s1) ? __expf(sf[nt][3]) : 0.0f;
                ls0 += sf[nt][0] + sf[nt][1];
                ls1 += sf[nt][2] + sf[nt][3];
            }
        } else {
            #pragma unroll
            for (int nt = 0; nt < 8; ++nt) {
                sf[nt][0] = __expf(sf[nt][0]);
                sf[nt][1] = __expf(sf[nt][1]);
                sf[nt][2] = __expf(sf[nt][2]);
                sf[nt][3] = __expf(sf[nt][3]);
                ls0 += sf[nt][0] + sf[nt][1];
                ls1 += sf[nt][2] + sf[nt][3];
            }
        }

        // ---- O += P V : tf32; P via quad shuffles, V via LDS.128 ----
        const int srcA = (lane & ~3) | (lc >> 1);
        const int srcB = srcA + 2;
        const bool odd = (lc & 1);
        #pragma unroll
        for (int ks = 0; ks < 8; ++ks) {
            const float v0 = __shfl_sync(0xffffffffu, sf[ks][0], srcA);
            const float v1 = __shfl_sync(0xffffffffu, sf[ks][1], srcA);
            const float v2 = __shfl_sync(0xffffffffu, sf[ks][2], srcA);
            const float v3 = __shfl_sync(0xffffffffu, sf[ks][3], srcA);
            const float w0 = __shfl_sync(0xffffffffu, sf[ks][0], srcB);
            const float w1 = __shfl_sync(0xffffffffu, sf[ks][1], srcB);
            const float w2 = __shfl_sync(0xffffffffu, sf[ks][2], srcB);
            const float w3 = __shfl_sync(0xffffffffu, sf[ks][3], srcB);
            const unsigned A0 = f2tf32(odd ? v1 : v0);
            const unsigned A1 = f2tf32(odd ? v3 : v2);
            const unsigned A2 = f2tf32(odd ? w1 : w0);
            const unsigned A3 = f2tf32(odd ? w3 : w2);
            const float4* vb0 = (const float4*)(Vp + (ks * 8 + lc)     * VSTR) + lr * 4;
            const float4* vb1 = (const float4*)(Vp + (ks * 8 + 4 + lc) * VSTR) + lr * 4;
            #pragma unroll
            for (int g = 0; g < 4; ++g) {
                const float4 B0 = vb0[g];
                const float4 B1 = vb1[g];
                mma_tf32(oacc[g * 4 + 0], A0, A1, A2, A3, __float_as_uint(B0.x), __float_as_uint(B1.x));
                mma_tf32(oacc[g * 4 + 1], A0, A1, A2, A3, __float_as_uint(B0.y), __float_as_uint(B1.y));
                mma_tf32(oacc[g * 4 + 2], A0, A1, A2, A3, __float_as_uint(B0.z), __float_as_uint(B1.z));
                mma_tf32(oacc[g * 4 + 3], A0, A1, A2, A3, __float_as_uint(B0.w), __float_as_uint(B1.w));
            }
        }
    }

    // ---- epilogue ----
    ls0 += __shfl_xor_sync(0xffffffffu, ls0, 1);
    ls0 += __shfl_xor_sync(0xffffffffu, ls0, 2);
    ls1 += __shfl_xor_sync(0xffffffffu, ls1, 1);
    ls1 += __shfl_xor_sync(0xffffffffu, ls1, 2);
    const float linv0 = 1.0f / ls0;
    const float linv1 = 1.0f / ls1;
    float* O0 = O + ((size_t)s0 * HEADS + h) * DIM;
    float* O1 = O + ((size_t)s1 * HEADS + h) * DIM;
    #pragma unroll
    for (int nt = 0; nt < 16; ++nt) {
        const int col = nt * 8 + lc * 2;
        *(float2*)(O0 + col) = make_float2(oacc[nt][0] * linv0, oacc[nt][1] * linv0);
        *(float2*)(O1 + col) = make_float2(oacc[nt][2] * linv1, oacc[nt][3] * linv1);
    }
}

extern "C" void kernel_launch(void* const* d_in, const int* in_sizes, int n_in,
                              void* d_out, int out_size) {
    const float* Q = (const float*)d_in[0];
    const float* K = (const float*)d_in[1];
    const float* V = (const float*)d_in[2];
    float* O = (float*)d_out;

    const size_t smem = SMEM_FLOATS * sizeof(float);   // 70656 B
    static bool attr_set = false;
    if (!attr_set) {
        cudaFuncSetAttribute(sparse_attn_cp_kernel,
                             cudaFuncAttributeMaxDynamicSharedMemorySize, (int)smem);
        attr_set = true;
    }

    // prepass: 65536 rows x 32 jobs = 2M threads
    prepack_kernel<<<8192, 256>>>(K, V);
    dim3 grid(32, HEADS);
    sparse_attn_cp_kernel<<<grid, 128, smem>>>(Q, O);
}

// round 9
// speedup vs baseline: 1.1015x; 1.1015x over previous
#include <cuda_runtime.h>
#include <cstdint>

#define HEADS 32
#define S_LEN 2048
#define DIM   128
#define LOCAL 16

#define KSTR 144   // smem words per K row (packed), 144%32==16 -> conflict-free LDS.128
#define VSTR 132   // smem words per V row (permuted), 132%16==4
#define SMEM_WORDS (2*64*KSTR + 64*VSTR)   // 26880 words = 107520 B

// precomputed per-(head,token) rows, tile-ready
__device__ unsigned g_Kpack[(size_t)HEADS * S_LEN * DIM];   // 32 MB
__device__ unsigned g_Vperm[(size_t)HEADS * S_LEN * DIM];   // 32 MB

__device__ __forceinline__ unsigned f2tf32(float x) {
    unsigned r; asm("cvt.rna.tf32.f32 %0, %1;" : "=r"(r) : "f"(x)); return r;
}
__device__ __forceinline__ unsigned pack_bf16x2(float lo_el, float hi_el) {
    unsigned r; asm("cvt.rn.bf16x2.f32 %0, %1, %2;" : "=r"(r) : "f"(hi_el), "f"(lo_el)); return r;
}
__device__ __forceinline__ float bf2f_lo(unsigned w) { return __uint_as_float(w << 16); }
__device__ __forceinline__ float bf2f_hi(unsigned w) { return __uint_as_float(w & 0xFFFF0000u); }
__device__ __forceinline__ void split2(float x0, float x1, unsigned& wh, unsigned& wl) {
    wh = pack_bf16x2(x0, x1);
    wl = pack_bf16x2(x0 - bf2f_lo(wh), x1 - bf2f_hi(wh));
}
__device__ __forceinline__ void mma_bf16(float c[4],
                                         unsigned a0, unsigned a1, unsigned a2, unsigned a3,
                                         unsigned b0, unsigned b1) {
    asm volatile(
        "mma.sync.aligned.m16n8k16.row.col.f32.bf16.bf16.f32 "
        "{%0,%1,%2,%3}, {%4,%5,%6,%7}, {%8,%9}, {%0,%1,%2,%3};"
        : "+f"(c[0]), "+f"(c[1]), "+f"(c[2]), "+f"(c[3])
        : "r"(a0), "r"(a1), "r"(a2), "r"(a3), "r"(b0), "r"(b1));
}
__device__ __forceinline__ void mma_tf32(float c[4],
                                         unsigned a0, unsigned a1, unsigned a2, unsigned a3,
                                         unsigned b0, unsigned b1) {
    asm volatile(
        "mma.sync.aligned.m16n8k8.row.col.f32.tf32.tf32.f32 "
        "{%0,%1,%2,%3}, {%4,%5,%6,%7}, {%8,%9}, {%0,%1,%2,%3};"
        : "+f"(c[0]), "+f"(c[1]), "+f"(c[2]), "+f"(c[3])
        : "r"(a0), "r"(a1), "r"(a2), "r"(a3), "r"(b0), "r"(b1));
}
__device__ __forceinline__ uint32_t smem_u32(const void* p) {
    uint32_t a;
    asm("{ .reg .u64 t; cvta.to.shared.u64 t, %1; cvt.u32.u64 %0, t; }" : "=r"(a) : "l"(p));
    return a;
}
__device__ __forceinline__ void cp16(uint32_t dst, const void* src) {
    asm volatile("cp.async.ca.shared.global [%0], [%1], 16;" :: "r"(dst), "l"(src));
}
#define CP_COMMIT() asm volatile("cp.async.commit_group;" ::: "memory")
#define CP_WAIT(N)  asm volatile("cp.async.wait_group %0;" :: "n"(N) : "memory")

// ---- prepass: K -> bf16 hi/lo packed; V -> tf32 permuted ----
__global__ __launch_bounds__(256)
void prepack_kernel(const float* __restrict__ K, const float* __restrict__ V) {
    const int gid = blockIdx.x * 256 + threadIdx.x;
    const int rid = gid >> 5;
    const int j   = gid & 31;
    const int h   = rid >> 11;
    const int s   = rid & 2047;
    const size_t src_row = ((size_t)s * HEADS + h) * DIM;
    const size_t dst_row = (size_t)rid * DIM;

    const float4 k4 = __ldg((const float4*)(K + src_row) + j);
    unsigned h1, l1, h2, l2;
    split2(k4.x, k4.y, h1, l1);
    split2(k4.z, k4.w, h2, l2);
    *(uint4*)&g_Kpack[dst_row + j * 4] = make_uint4(h1, l1, h2, l2);

    unsigned vw[4];
    #pragma unroll
    for (int m = 0; m < 4; ++m) {
        const int p = 4 * j + m;
        const int d = ((p & 15) << 3) | (p >> 4);
        vw[m] = f2tf32(__ldg(V + src_row + d));
    }
    *(uint4*)&g_Vperm[dst_row + j * 4] = make_uint4(vw[0], vw[1], vw[2], vw[3]);
}

__global__ __launch_bounds__(128, 2)
void sparse_attn_db_kernel(const float* __restrict__ Q,
                           float* __restrict__ O) {
    extern __shared__ float sm[];
    float* Kbuf[2] = { sm, sm + 64 * KSTR };
    float* Vp = sm + 2 * 64 * KSTR;
    const uint32_t sbK0 = smem_u32(Kbuf[0]);
    const uint32_t sbK1 = smem_u32(Kbuf[1]);
    const uint32_t sbV  = smem_u32(Vp);

    const int qb   = blockIdx.x;
    const int h    = blockIdx.y;
    const int t    = threadIdx.x;   // 0..127
    const int lane = t & 31;
    const int lr   = lane >> 2;
    const int lc   = lane & 3;

    const int w   = t >> 5;
    const int s0  = qb * 64 + w * 16 + lr;
    const int s1  = s0 + 8;
    const float scale = 0.08838834764831845f;

    const size_t hbase = (size_t)h * S_LEN * DIM;
    // per-thread source/dest offsets for the 16-copy loops (idx = t + it*128)
    // r = idx>>5, c = idx&31

    // ---- Q fragments in registers (scaled, split hi/lo) ----
    unsigned qa0[8][4], qa1[8][4];
    {
        const float* Qp0 = Q + ((size_t)s0 * HEADS + h) * DIM;
        const float* Qp1 = Q + ((size_t)s1 * HEADS + h) * DIM;
        #pragma unroll
        for (int kg = 0; kg < 8; ++kg) {
            const float4 A = *(const float4*)(Qp0 + kg * 16 + lc * 4);
            const float4 B = *(const float4*)(Qp1 + kg * 16 + lc * 4);
            split2(A.x * scale, A.y * scale, qa0[kg][0], qa0[kg][1]);
            split2(A.z * scale, A.w * scale, qa0[kg][2], qa0[kg][3]);
            split2(B.x * scale, B.y * scale, qa1[kg][0], qa1[kg][1]);
            split2(B.z * scale, B.w * scale, qa1[kg][2], qa1[kg][3]);
        }
    }

    float oacc[16][4];
    #pragma unroll
    for (int nt = 0; nt < 16; ++nt)
        #pragma unroll
        for (int j = 0; j < 4; ++j) oacc[nt][j] = 0.0f;
    float ls0 = 0.0f, ls1 = 0.0f;

    // ---- first allowed kv block ----
    int kb = 0;
    while (!(((qb - kb) < LOCAL) || (((kb + h + 1) & 7) == 0))) ++kb;

    // preload K(kb) into buffer 0
    {
        const unsigned* gK = g_Kpack + hbase + (size_t)kb * 64 * DIM;
        #pragma unroll
        for (int it = 0; it < 16; ++it) {
            const int idx = t + it * 128;
            const int r = idx >> 5, c = idx & 31;
            cp16(sbK0 + (r * KSTR + c * 4) * 4, gK + r * DIM + c * 4);
        }
        CP_COMMIT();
    }

    int cur = 0;
    while (kb >= 0) {
        int kbn = kb + 1;
        while (kbn <= qb && !(((qb - kbn) < LOCAL) || (((kbn + h + 1) & 7) == 0))) ++kbn;
        if (kbn > qb) kbn = -1;

        CP_WAIT(0);         // K(kb) resident (this thread); V buffer free after barrier
        __syncthreads();    // all threads' K copies visible; PV(i-1) fully done

        // ---- issue V(kb) and K(kbn) cp.async (overlap with QK below) ----
        {
            const unsigned* gV = g_Vperm + hbase + (size_t)kb * 64 * DIM;
            #pragma unroll
            for (int it = 0; it < 16; ++it) {
                const int idx = t + it * 128;
                const int r = idx >> 5, c = idx & 31;
                cp16(sbV + (r * VSTR + c * 4) * 4, gV + r * DIM + c * 4);
            }
            CP_COMMIT();    // group: V
        }
        if (kbn >= 0) {
            const uint32_t dstK = cur ? sbK0 : sbK1;
            const unsigned* gK = g_Kpack + hbase + (size_t)kbn * 64 * DIM;
            #pragma unroll
            for (int it = 0; it < 16; ++it) {
                const int idx = t + it * 128;
                const int r = idx >> 5, c = idx & 31;
                cp16(dstK + (r * KSTR + c * 4) * 4, gK + r * DIM + c * 4);
            }
            CP_COMMIT();    // group: K(next)
        }

        // ---- S = Q K^T : 3-term bf16 split ----
        const unsigned* Ku = (const unsigned*)Kbuf[cur];
        float sf[8][4];
        #pragma unroll
        for (int nt = 0; nt < 8; ++nt)
            #pragma unroll
            for (int j = 0; j < 4; ++j) sf[nt][j] = 0.0f;

        #pragma unroll
        for (int kg = 0; kg < 8; ++kg) {
            #pragma unroll
            for (int nt = 0; nt < 8; ++nt) {
                const uint4 B = *(const uint4*)&Ku[(nt * 8 + lr) * KSTR + kg * 16 + lc * 4];
                mma_bf16(sf[nt], qa0[kg][0], qa1[kg][0], qa0[kg][2], qa1[kg][2], B.x, B.z);
                mma_bf16(sf[nt], qa0[kg][0], qa1[kg][0], qa0[kg][2], qa1[kg][2], B.y, B.w);
                mma_bf16(sf[nt], qa0[kg][1], qa1[kg][1], qa0[kg][3], qa1[kg][3], B.x, B.z);
            }
        }

        // ---- softmax in registers (fixed-max; shift-invariant) ----
        if (kb == qb) {
            #pragma unroll
            for (int nt = 0; nt < 8; ++nt) {
                const int c0 = kb * 64 + nt * 8 + lc * 2;
                sf[nt][0] = (c0     <= s0) ? __expf(sf[nt][0]) : 0.0f;
                sf[nt][1] = (c0 + 1 <= s0) ? __expf(sf[nt][1]) : 0.0f;
                sf[nt][2] = (c0     <= s1) ? __expf(sf[nt][2]) : 0.0f;
                sf[nt][3] = (c0 + 1 <= s1) ? __expf(sf[nt][3]) : 0.0f;
                ls0 += sf[nt][0] + sf[nt][1];
                ls1 += sf[nt][2] + sf[nt][3];
            }
        } else {
            #pragma unroll
            for (int nt = 0; nt < 8; ++nt) {
                sf[nt][0] = __expf(sf[nt][0]);
                sf[nt][1] = __expf(sf[nt][1]);
                sf[nt][2] = __expf(sf[nt][2]);
                sf[nt][3] = __expf(sf[nt][3]);
                ls0 += sf[nt][0] + sf[nt][1];
                ls1 += sf[nt][2] + sf[nt][3];
            }
        }

        // ---- wait V (K(next) may stay pending), sync, then PV ----
        if (kbn >= 0) { CP_WAIT(1); } else { CP_WAIT(0); }
        __syncthreads();

        const int srcA = (lane & ~3) | (lc >> 1);
        const int srcB = srcA + 2;
        const bool odd = (lc & 1);
        #pragma unroll
        for (int ks = 0; ks < 8; ++ks) {
            const float v0 = __shfl_sync(0xffffffffu, sf[ks][0], srcA);
            const float v1 = __shfl_sync(0xffffffffu, sf[ks][1], srcA);
            const float v2 = __shfl_sync(0xffffffffu, sf[ks][2], srcA);
            const float v3 = __shfl_sync(0xffffffffu, sf[ks][3], srcA);
            const float w0 = __shfl_sync(0xffffffffu, sf[ks][0], srcB);
            const float w1 = __shfl_sync(0xffffffffu, sf[ks][1], srcB);
            const float w2 = __shfl_sync(0xffffffffu, sf[ks][2], srcB);
            const float w3 = __shfl_sync(0xffffffffu, sf[ks][3], srcB);
            const unsigned A0 = f2tf32(odd ? v1 : v0);
            const unsigned A1 = f2tf32(odd ? v3 : v2);
            const unsigned A2 = f2tf32(odd ? w1 : w0);
            const unsigned A3 = f2tf32(odd ? w3 : w2);
            const float4* vb0 = (const float4*)(Vp + (ks * 8 + lc)     * VSTR) + lr * 4;
            const float4* vb1 = (const float4*)(Vp + (ks * 8 + 4 + lc) * VSTR) + lr * 4;
            #pragma unroll
            for (int g = 0; g < 4; ++g) {
                const float4 B0 = vb0[g];
                const float4 B1 = vb1[g];
                mma_tf32(oacc[g * 4 + 0], A0, A1, A2, A3, __float_as_uint(B0.x), __float_as_uint(B1.x));
                mma_tf32(oacc[g * 4 + 1], A0, A1, A2, A3, __float_as_uint(B0.y), __float_as_uint(B1.y));
                mma_tf32(oacc[g * 4 + 2], A0, A1, A2, A3, __float_as_uint(B0.z), __float_as_uint(B1.z));
                mma_tf32(oacc[g * 4 + 3], A0, A1, A2, A3, __float_as_uint(B0.w), __float_as_uint(B1.w));
            }
        }

        kb = kbn;
        cur ^= 1;
    }

    // ---- epilogue ----
    ls0 += __shfl_xor_sync(0xffffffffu, ls0, 1);
    ls0 += __shfl_xor_sync(0xffffffffu, ls0, 2);
    ls1 += __shfl_xor_sync(0xffffffffu, ls1, 1);
    ls1 += __shfl_xor_sync(0xffffffffu, ls1, 2);
    const float linv0 = 1.0f / ls0;
    const float linv1 = 1.0f / ls1;
    float* O0 = O + ((size_t)s0 * HEADS + h) * DIM;
    float* O1 = O + ((size_t)s1 * HEADS + h) * DIM;
    #pragma unroll
    for (int nt = 0; nt < 16; ++nt) {
        const int col = nt * 8 + lc * 2;
        *(float2*)(O0 + col) = make_float2(oacc[nt][0] * linv0, oacc[nt][1] * linv0);
        *(float2*)(O1 + col) = make_float2(oacc[nt][2] * linv1, oacc[nt][3] * linv1);
    }
}

extern "C" void kernel_launch(void* const* d_in, const int* in_sizes, int n_in,
                              void* d_out, int out_size) {
    const float* Q = (const float*)d_in[0];
    const float* K = (const float*)d_in[1];
    const float* V = (const float*)d_in[2];
    float* O = (float*)d_out;

    const size_t smem = SMEM_WORDS * sizeof(float);   // 107520 B
    static bool attr_set = false;
    if (!attr_set) {
        cudaFuncSetAttribute(sparse_attn_db_kernel,
                             cudaFuncAttributeMaxDynamicSharedMemorySize, (int)smem);
        attr_set = true;
    }

    prepack_kernel<<<8192, 256>>>(K, V);
    dim3 grid(32, HEADS);
    sparse_attn_db_kernel<<<grid, 128, smem>>>(Q, O);
}

// round 10
// speedup vs baseline: 1.4848x; 1.3479x over previous
#include <cuda_runtime.h>
#include <cstdint>

#define HEADS 32
#define S_LEN 2048
#define DIM   128
#define LOCAL 16

#define KSTR 80    // words per K row (fp16x2), 80: lanes' 16B chunks lr*20+lc distinct mod 8
#define VSTR 132   // words per V row (permuted tf32), 132%16==4
#define KBUF (64*KSTR)
#define VBUF (64*VSTR)
#define SMEM_WORDS (2*KBUF + 2*VBUF)   // 27136 words = 108544 B

__device__ unsigned g_Kp16 [(size_t)HEADS * S_LEN * 64];    // 16 MB (fp16x2 packed)
__device__ unsigned g_Vperm[(size_t)HEADS * S_LEN * DIM];   // 32 MB (tf32 permuted)

__device__ __forceinline__ unsigned f2tf32(float x) {
    unsigned r; asm("cvt.rna.tf32.f32 %0, %1;" : "=r"(r) : "f"(x)); return r;
}
// pack two floats into fp16x2, low half = first arg
__device__ __forceinline__ unsigned pack_f16x2(float lo_el, float hi_el) {
    unsigned r; asm("cvt.rn.f16x2.f32 %0, %1, %2;" : "=r"(r) : "f"(hi_el), "f"(lo_el)); return r;
}
__device__ __forceinline__ void mma_f16(float c[4],
                                        unsigned a0, unsigned a1, unsigned a2, unsigned a3,
                                        unsigned b0, unsigned b1) {
    asm volatile(
        "mma.sync.aligned.m16n8k16.row.col.f32.f16.f16.f32 "
        "{%0,%1,%2,%3}, {%4,%5,%6,%7}, {%8,%9}, {%0,%1,%2,%3};"
        : "+f"(c[0]), "+f"(c[1]), "+f"(c[2]), "+f"(c[3])
        : "r"(a0), "r"(a1), "r"(a2), "r"(a3), "r"(b0), "r"(b1));
}
__device__ __forceinline__ void mma_tf32(float c[4],
                                         unsigned a0, unsigned a1, unsigned a2, unsigned a3,
                                         unsigned b0, unsigned b1) {
    asm volatile(
        "mma.sync.aligned.m16n8k8.row.col.f32.tf32.tf32.f32 "
        "{%0,%1,%2,%3}, {%4,%5,%6,%7}, {%8,%9}, {%0,%1,%2,%3};"
        : "+f"(c[0]), "+f"(c[1]), "+f"(c[2]), "+f"(c[3])
        : "r"(a0), "r"(a1), "r"(a2), "r"(a3), "r"(b0), "r"(b1));
}
__device__ __forceinline__ uint32_t smem_u32(const void* p) {
    uint32_t a;
    asm("{ .reg .u64 t; cvta.to.shared.u64 t, %1; cvt.u32.u64 %0, t; }" : "=r"(a) : "l"(p));
    return a;
}
__device__ __forceinline__ void cp16(uint32_t dst, const void* src) {
    asm volatile("cp.async.ca.shared.global [%0], [%1], 16;" :: "r"(dst), "l"(src));
}
#define CP_COMMIT() asm volatile("cp.async.commit_group;" ::: "memory")
#define CP_WAIT0()  asm volatile("cp.async.wait_group 0;" ::: "memory")

// ---- prepass: K -> fp16x2 mma-ready; V -> tf32 permuted ----
// K row layout (64 words): word i: p=i>>4, lc=(i>>2)&3, s=i&3, kg=2p+(s>>1),
//   d = kg*16 + lc*4 + (s&1)*2 -> f16x2(K[d], K[d+1])
__global__ __launch_bounds__(256)
void prepack16_kernel(const float* __restrict__ K, const float* __restrict__ V) {
    const int gid = blockIdx.x * 256 + threadIdx.x;
    const int rid = gid >> 5;
    const int j   = gid & 31;
    const int h   = rid >> 11;
    const int s   = rid & 2047;
    const size_t src_row = ((size_t)s * HEADS + h) * DIM;

    // V permuted p = (d&7)*16 + (d>>3)
    unsigned vw[4];
    #pragma unroll
    for (int m = 0; m < 4; ++m) {
        const int p = 4 * j + m;
        const int d = ((p & 15) << 3) | (p >> 4);
        vw[m] = f2tf32(__ldg(V + src_row + d));
    }
    *(uint4*)&g_Vperm[(size_t)rid * DIM + j * 4] = make_uint4(vw[0], vw[1], vw[2], vw[3]);

    if (j < 16) {
        unsigned kw[4];
        #pragma unroll
        for (int m = 0; m < 4; ++m) {
            const int i  = 4 * j + m;
            const int p  = i >> 4;
            const int lc = (i >> 2) & 3;
            const int s2 = i & 3;
            const int kg = 2 * p + (s2 >> 1);
            const int d  = kg * 16 + lc * 4 + (s2 & 1) * 2;
            const float2 v = __ldg((const float2*)(K + src_row + d));
            kw[m] = pack_f16x2(v.x, v.y);
        }
        *(uint4*)&g_Kp16[(size_t)rid * 64 + j * 4] = make_uint4(kw[0], kw[1], kw[2], kw[3]);
    }
}

__global__ __launch_bounds__(128, 2)
void sparse_attn_f16_kernel(const float* __restrict__ Q,
                            float* __restrict__ O) {
    extern __shared__ float sm[];
    unsigned* Kb[2] = { (unsigned*)sm, (unsigned*)sm + KBUF };
    float*    Vb[2] = { sm + 2 * KBUF, sm + 2 * KBUF + VBUF };
    const uint32_t sbK[2] = { smem_u32(Kb[0]), smem_u32(Kb[1]) };
    const uint32_t sbV[2] = { smem_u32(Vb[0]), smem_u32(Vb[1]) };

    const int qb   = blockIdx.x;
    const int h    = blockIdx.y;
    const int t    = threadIdx.x;   // 0..127
    const int w    = t >> 5;
    const int lane = t & 31;
    const int lr   = lane >> 2;
    const int lc   = lane & 3;

    const int s0  = qb * 64 + w * 16 + lr;
    const int s1  = s0 + 8;
    const float scale = 0.08838834764831845f;
    const size_t hK = (size_t)h * S_LEN * 64;
    const size_t hV = (size_t)h * S_LEN * DIM;

    // ---- Q fragments in registers, fp16x2 (scale folded) ----
    unsigned qa[8][4];   // [kg][a0..a3]
    {
        const float* Qp0 = Q + ((size_t)s0 * HEADS + h) * DIM;
        const float* Qp1 = Q + ((size_t)s1 * HEADS + h) * DIM;
        #pragma unroll
        for (int kg = 0; kg < 8; ++kg) {
            const float4 A = *(const float4*)(Qp0 + kg * 16 + lc * 4);
            const float4 B = *(const float4*)(Qp1 + kg * 16 + lc * 4);
            qa[kg][0] = pack_f16x2(A.x * scale, A.y * scale);
            qa[kg][1] = pack_f16x2(B.x * scale, B.y * scale);
            qa[kg][2] = pack_f16x2(A.z * scale, A.w * scale);
            qa[kg][3] = pack_f16x2(B.z * scale, B.w * scale);
        }
    }

    float oacc[16][4];
    #pragma unroll
    for (int nt = 0; nt < 16; ++nt)
        #pragma unroll
        for (int j = 0; j < 4; ++j) oacc[nt][j] = 0.0f;
    float ls0 = 0.0f, ls1 = 0.0f;

    // ---- first allowed kv block; prologue issue into buffer 0 ----
    int kb = 0;
    while (!(((qb - kb) < LOCAL) || (((kb + h + 1) & 7) == 0))) ++kb;
    {
        const unsigned* gK = g_Kp16 + hK + (size_t)kb * 64 * 64;
        const unsigned* gV = g_Vperm + hV + (size_t)kb * 64 * DIM;
        #pragma unroll
        for (int it = 0; it < 8; ++it) {          // K: 1024 words
            const int c = t + it * 128;
            const int r = c >> 4, w4 = c & 15;
            cp16(sbK[0] + (r * KSTR + w4 * 4) * 4, gK + r * 64 + w4 * 4);
        }
        #pragma unroll
        for (int it = 0; it < 16; ++it) {         // V: 2048 words
            const int c = t + it * 128;
            const int r = c >> 5, w4 = c & 31;
            cp16(sbV[0] + (r * VSTR + w4 * 4) * 4, gV + r * DIM + w4 * 4);
        }
        CP_COMMIT();
    }

    int cur = 0;
    while (kb >= 0) {
        int kbn = kb + 1;
        while (kbn <= qb && !(((qb - kbn) < LOCAL) || (((kbn + h + 1) & 7) == 0))) ++kbn;
        if (kbn > qb) kbn = -1;

        CP_WAIT0();          // tiles (kb) resident
        __syncthreads();     // visible to all; prior compute on other buffer done

        // ---- issue next tiles into the other buffer (overlaps compute) ----
        if (kbn >= 0) {
            const int nb = cur ^ 1;
            const unsigned* gK = g_Kp16 + hK + (size_t)kbn * 64 * 64;
            const unsigned* gV = g_Vperm + hV + (size_t)kbn * 64 * DIM;
            #pragma unroll
            for (int it = 0; it < 8; ++it) {
                const int c = t + it * 128;
                const int r = c >> 4, w4 = c & 15;
                cp16(sbK[nb] + (r * KSTR + w4 * 4) * 4, gK + r * 64 + w4 * 4);
            }
            #pragma unroll
            for (int it = 0; it < 16; ++it) {
                const int c = t + it * 128;
                const int r = c >> 5, w4 = c & 31;
                cp16(sbV[nb] + (r * VSTR + w4 * 4) * 4, gV + r * DIM + w4 * 4);
            }
            CP_COMMIT();
        }

        // ---- S = Q K^T : single-term fp16, m16n8k16 ----
        const unsigned* Ku = Kb[cur];
        float sf[8][4];
        #pragma unroll
        for (int nt = 0; nt < 8; ++nt)
            #pragma unroll
            for (int j = 0; j < 4; ++j) sf[nt][j] = 0.0f;

        #pragma unroll
        for (int p = 0; p < 4; ++p) {
            #pragma unroll
            for (int nt = 0; nt < 8; ++nt) {
                const uint4 B = *(const uint4*)&Ku[(nt * 8 + lr) * KSTR + p * 16 + lc * 4];
                mma_f16(sf[nt], qa[2*p][0],   qa[2*p][1],   qa[2*p][2],   qa[2*p][3],   B.x, B.y);
                mma_f16(sf[nt], qa[2*p+1][0], qa[2*p+1][1], qa[2*p+1][2], qa[2*p+1][3], B.z, B.w);
            }
        }

        // ---- softmax in registers (fixed-max; shift-invariant) ----
        if (kb == qb) {
            #pragma unroll
            for (int nt = 0; nt < 8; ++nt) {
                const int c0 = kb * 64 + nt * 8 + lc * 2;
                sf[nt][0] = (c0     <= s0) ? __expf(sf[nt][0]) : 0.0f;
                sf[nt][1] = (c0 + 1 <= s0) ? __expf(sf[nt][1]) : 0.0f;
                sf[nt][2] = (c0     <= s1) ? __expf(sf[nt][2]) : 0.0f;
                sf[nt][3] = (c0 + 1 <= s1) ? __expf(sf[nt][3]) : 0.0f;
                ls0 += sf[nt][0] + sf[nt][1];
                ls1 += sf[nt][2] + sf[nt][3];
            }
        } else {
            #pragma unroll
            for (int nt = 0; nt < 8; ++nt) {
                sf[nt][0] = __expf(sf[nt][0]);
                sf[nt][1] = __expf(sf[nt][1]);
                sf[nt][2] = __expf(sf[nt][2]);
                sf[nt][3] = __expf(sf[nt][3]);
                ls0 += sf[nt][0] + sf[nt][1];
                ls1 += sf[nt][2] + sf[nt][3];
            }
        }

        // ---- O += P V : tf32; P via quad shuffles, V via LDS.128 (permuted) ----
        const float* Vp = Vb[cur];
        const int srcA = (lane & ~3) | (lc >> 1);
        const int srcB = srcA + 2;
        const bool odd = (lc & 1);
        #pragma unroll
        for (int ks = 0; ks < 8; ++ks) {
            const float v0 = __shfl_sync(0xffffffffu, sf[ks][0], srcA);
            const float v1 = __shfl_sync(0xffffffffu, sf[ks][1], srcA);
            const float v2 = __shfl_sync(0xffffffffu, sf[ks][2], srcA);
            const float v3 = __shfl_sync(0xffffffffu, sf[ks][3], srcA);
            const float w0 = __shfl_sync(0xffffffffu, sf[ks][0], srcB);
            const float w1 = __shfl_sync(0xffffffffu, sf[ks][1], srcB);
            const float w2 = __shfl_sync(0xffffffffu, sf[ks][2], srcB);
            const float w3 = __shfl_sync(0xffffffffu, sf[ks][3], srcB);
            const unsigned A0 = f2tf32(odd ? v1 : v0);
            const unsigned A1 = f2tf32(odd ? v3 : v2);
            const unsigned A2 = f2tf32(odd ? w1 : w0);
            const unsigned A3 = f2tf32(odd ? w3 : w2);
            const float4* vb0 = (const float4*)(Vp + (ks * 8 + lc)     * VSTR) + lr * 4;
            const float4* vb1 = (const float4*)(Vp + (ks * 8 + 4 + lc) * VSTR) + lr * 4;
            #pragma unroll
            for (int g = 0; g < 4; ++g) {
                const float4 B0 = vb0[g];
                const float4 B1 = vb1[g];
                mma_tf32(oacc[g * 4 + 0], A0, A1, A2, A3, __float_as_uint(B0.x), __float_as_uint(B1.x));
                mma_tf32(oacc[g * 4 + 1], A0, A1, A2, A3, __float_as_uint(B0.y), __float_as_uint(B1.y));
                mma_tf32(oacc[g * 4 + 2], A0, A1, A2, A3, __float_as_uint(B0.z), __float_as_uint(B1.z));
                mma_tf32(oacc[g * 4 + 3], A0, A1, A2, A3, __float_as_uint(B0.w), __float_as_uint(B1.w));
            }
        }

        kb = kbn;
        cur ^= 1;
    }

    // ---- epilogue ----
    ls0 += __shfl_xor_sync(0xffffffffu, ls0, 1);
    ls0 += __shfl_xor_sync(0xffffffffu, ls0, 2);
    ls1 += __shfl_xor_sync(0xffffffffu, ls1, 1);
    ls1 += __shfl_xor_sync(0xffffffffu, ls1, 2);
    const float linv0 = 1.0f / ls0;
    const float linv1 = 1.0f / ls1;
    float* O0 = O + ((size_t)s0 * HEADS + h) * DIM;
    float* O1 = O + ((size_t)s1 * HEADS + h) * DIM;
    #pragma unroll
    for (int nt = 0; nt < 16; ++nt) {
        const int col = nt * 8 + lc * 2;
        *(float2*)(O0 + col) = make_float2(oacc[nt][0] * linv0, oacc[nt][1] * linv0);
        *(float2*)(O1 + col) = make_float2(oacc[nt][2] * linv1, oacc[nt][3] * linv1);
    }
}

extern "C" void kernel_launch(void* const* d_in, const int* in_sizes, int n_in,
                              void* d_out, int out_size) {
    const float* Q = (const float*)d_in[0];
    const float* K = (const float*)d_in[1];
    const float* V = (const float*)d_in[2];
    float* O = (float*)d_out;

    const size_t smem = SMEM_WORDS * sizeof(float);   // 108544 B
    static bool attr_set = false;
    if (!attr_set) {
        cudaFuncSetAttribute(sparse_attn_f16_kernel,
                             cudaFuncAttributeMaxDynamicSharedMemorySize, (int)smem);
        attr_set = true;
    }

    prepack16_kernel<<<8192, 256>>>(K, V);
    dim3 grid(32, HEADS);
    sparse_attn_f16_kernel<<<grid, 128, smem>>>(Q, O);
}

// round 11
// speedup vs baseline: 2.2528x; 1.5173x over previous
#include <cuda_runtime.h>
#include <cstdint>

#define HEADS 32
#define S_LEN 2048
#define DIM   128
#define LOCAL 16

#define KSTR  80   // words per K row (fp16x2 packed), padded
#define VSTR16 36  // words per V16 dim-row (32 data words + 4 pad); (lr+2lc) distinct mod 8
#define KBUF  (64*KSTR)        // 5120 words
#define VBUF  (128*VSTR16)     // 4608 words
#define SMEM_WORDS (2*KBUF + 2*VBUF)   // 19456 words = 77824 B

__device__ unsigned g_Kp16[(size_t)HEADS * S_LEN * 64];          // 16 MB fp16x2 mma-ready
__device__ unsigned g_V16 [(size_t)HEADS * 32 * 128 * 32];       // 16 MB fp16x2 [h,kb][dim][w']

__device__ __forceinline__ unsigned pack_f16x2(float lo_el, float hi_el) {
    unsigned r; asm("cvt.rn.f16x2.f32 %0, %1, %2;" : "=r"(r) : "f"(hi_el), "f"(lo_el)); return r;
}
__device__ __forceinline__ void mma_f16(float c[4],
                                        unsigned a0, unsigned a1, unsigned a2, unsigned a3,
                                        unsigned b0, unsigned b1) {
    asm volatile(
        "mma.sync.aligned.m16n8k16.row.col.f32.f16.f16.f32 "
        "{%0,%1,%2,%3}, {%4,%5,%6,%7}, {%8,%9}, {%0,%1,%2,%3};"
        : "+f"(c[0]), "+f"(c[1]), "+f"(c[2]), "+f"(c[3])
        : "r"(a0), "r"(a1), "r"(a2), "r"(a3), "r"(b0), "r"(b1));
}
__device__ __forceinline__ uint32_t smem_u32(const void* p) {
    uint32_t a;
    asm("{ .reg .u64 t; cvta.to.shared.u64 t, %1; cvt.u32.u64 %0, t; }" : "=r"(a) : "l"(p));
    return a;
}
__device__ __forceinline__ void cp16(uint32_t dst, const void* src) {
    asm volatile("cp.async.ca.shared.global [%0], [%1], 16;" :: "r"(dst), "l"(src));
}
#define CP_COMMIT() asm volatile("cp.async.commit_group;" ::: "memory")
#define CP_WAIT0()  asm volatile("cp.async.wait_group 0;" ::: "memory")

// ---- prepass K: fp16x2 mma-ready rows (64 words/row) ----
__global__ __launch_bounds__(256)
void prepackK16_kernel(const float* __restrict__ K) {
    const int gid = blockIdx.x * 256 + threadIdx.x;   // 1M: rid x 16
    const int rid = gid >> 4;        // h*2048 + s
    const int j   = gid & 15;
    const int h   = rid >> 11;
    const int s   = rid & 2047;
    const size_t src_row = ((size_t)s * HEADS + h) * DIM;
    unsigned kw[4];
    #pragma unroll
    for (int m = 0; m < 4; ++m) {
        const int i  = 4 * j + m;
        const int p  = i >> 4;
        const int lc = (i >> 2) & 3;
        const int s2 = i & 3;
        const int kg = 2 * p + (s2 >> 1);
        const int d  = kg * 16 + lc * 4 + (s2 & 1) * 2;
        const float2 v = __ldg((const float2*)(K + src_row + d));
        kw[m] = pack_f16x2(v.x, v.y);
    }
    *(uint4*)&g_Kp16[(size_t)rid * 64 + j * 4] = make_uint4(kw[0], kw[1], kw[2], kw[3]);
}

// ---- prepass V: fp16x2 token pairs, dim-major rows, word-permuted ----
// word w = f16x2(V[tok 2w], V[tok 2w+1]) stored at w' = (w&3)*8 + (w>>2)
__global__ __launch_bounds__(256)
void prepackV16_kernel(const float* __restrict__ V) {
    const int gid = blockIdx.x * 256 + threadIdx.x;   // 1M: rid x 1024
    const int rid = gid >> 10;       // h*32 + kb
    const int t2  = gid & 1023;
    const int d   = t2 & 127;
    const int j   = t2 >> 7;         // 0..7
    const int h   = rid >> 5;
    const int kb  = rid & 31;
    unsigned vw[4];
    #pragma unroll
    for (int m = 0; m < 4; ++m) {
        const int wp = 4 * j + m;                 // stored position
        const int w  = (wp >> 3) + (wp & 7) * 4;  // logical token pair
        const int tok = kb * 64 + 2 * w;
        const float a = __ldg(V + ((size_t)tok       * HEADS + h) * DIM + d);
        const float b = __ldg(V + ((size_t)(tok + 1) * HEADS + h) * DIM + d);
        vw[m] = pack_f16x2(a, b);
    }
    *(uint4*)&g_V16[((size_t)rid * 128 + d) * 32 + 4 * j] = make_uint4(vw[0], vw[1], vw[2], vw[3]);
}

__global__ __launch_bounds__(128, 2)
void sparse_attn_ff_kernel(const float* __restrict__ Q,
                           float* __restrict__ O) {
    extern __shared__ unsigned sm[];
    unsigned* Kb[2] = { sm, sm + KBUF };
    unsigned* Vb[2] = { sm + 2 * KBUF, sm + 2 * KBUF + VBUF };
    const uint32_t sbK[2] = { smem_u32(Kb[0]), smem_u32(Kb[1]) };
    const uint32_t sbV[2] = { smem_u32(Vb[0]), smem_u32(Vb[1]) };

    const int qb   = blockIdx.x;
    const int h    = blockIdx.y;
    const int t    = threadIdx.x;   // 0..127
    const int w    = t >> 5;
    const int lane = t & 31;
    const int lr   = lane >> 2;
    const int lc   = lane & 3;

    const int s0  = qb * 64 + w * 16 + lr;
    const int s1  = s0 + 8;
    const float scale = 0.08838834764831845f;
    const size_t hK = (size_t)h * S_LEN * 64;

    // ---- Q fragments in registers, fp16x2 (scale folded) ----
    unsigned qa[8][4];
    {
        const float* Qp0 = Q + ((size_t)s0 * HEADS + h) * DIM;
        const float* Qp1 = Q + ((size_t)s1 * HEADS + h) * DIM;
        #pragma unroll
        for (int kg = 0; kg < 8; ++kg) {
            const float4 A = *(const float4*)(Qp0 + kg * 16 + lc * 4);
            const float4 B = *(const float4*)(Qp1 + kg * 16 + lc * 4);
            qa[kg][0] = pack_f16x2(A.x * scale, A.y * scale);
            qa[kg][1] = pack_f16x2(B.x * scale, B.y * scale);
            qa[kg][2] = pack_f16x2(A.z * scale, A.w * scale);
            qa[kg][3] = pack_f16x2(B.z * scale, B.w * scale);
        }
    }

    float oacc[16][4];
    #pragma unroll
    for (int nt = 0; nt < 16; ++nt)
        #pragma unroll
        for (int j = 0; j < 4; ++j) oacc[nt][j] = 0.0f;
    float ls0 = 0.0f, ls1 = 0.0f;

    // ---- first allowed kv block; prologue issue into buffer 0 ----
    int kb = 0;
    while (!(((qb - kb) < LOCAL) || (((kb + h + 1) & 7) == 0))) ++kb;
    {
        const unsigned* gK = g_Kp16 + hK + (size_t)kb * 64 * 64;
        const unsigned* gV = g_V16 + ((size_t)(h * 32 + kb) * 128) * 32;
        #pragma unroll
        for (int it = 0; it < 8; ++it) {          // K: 1024 f4-words/4
            const int c = t + it * 128;
            const int r = c >> 4, w4 = c & 15;
            cp16(sbK[0] + (r * KSTR + w4 * 4) * 4, gK + r * 64 + w4 * 4);
        }
        #pragma unroll
        for (int it = 0; it < 8; ++it) {          // V16: 1024 copies
            const int c = t + it * 128;
            const int r = c >> 3, w4 = c & 7;
            cp16(sbV[0] + (r * VSTR16 + w4 * 4) * 4, gV + r * 32 + w4 * 4);
        }
        CP_COMMIT();
    }

    int cur = 0;
    while (kb >= 0) {
        int kbn = kb + 1;
        while (kbn <= qb && !(((qb - kbn) < LOCAL) || (((kbn + h + 1) & 7) == 0))) ++kbn;
        if (kbn > qb) kbn = -1;

        CP_WAIT0();          // tiles (kb) resident
        __syncthreads();     // visible; prior compute on other buffer done

        // ---- issue next tiles (overlaps compute) ----
        if (kbn >= 0) {
            const int nb = cur ^ 1;
            const unsigned* gK = g_Kp16 + hK + (size_t)kbn * 64 * 64;
            const unsigned* gV = g_V16 + ((size_t)(h * 32 + kbn) * 128) * 32;
            #pragma unroll
            for (int it = 0; it < 8; ++it) {
                const int c = t + it * 128;
                const int r = c >> 4, w4 = c & 15;
                cp16(sbK[nb] + (r * KSTR + w4 * 4) * 4, gK + r * 64 + w4 * 4);
            }
            #pragma unroll
            for (int it = 0; it < 8; ++it) {
                const int c = t + it * 128;
                const int r = c >> 3, w4 = c & 7;
                cp16(sbV[nb] + (r * VSTR16 + w4 * 4) * 4, gV + r * 32 + w4 * 4);
            }
            CP_COMMIT();
        }

        // ---- S = Q K^T : single-term fp16, m16n8k16 ----
        const unsigned* Ku = Kb[cur];
        float sf[8][4];
        #pragma unroll
        for (int nt = 0; nt < 8; ++nt)
            #pragma unroll
            for (int j = 0; j < 4; ++j) sf[nt][j] = 0.0f;

        #pragma unroll
        for (int p = 0; p < 4; ++p) {
            #pragma unroll
            for (int nt = 0; nt < 8; ++nt) {
                const uint4 B = *(const uint4*)&Ku[(nt * 8 + lr) * KSTR + p * 16 + lc * 4];
                mma_f16(sf[nt], qa[2*p][0],   qa[2*p][1],   qa[2*p][2],   qa[2*p][3],   B.x, B.y);
                mma_f16(sf[nt], qa[2*p+1][0], qa[2*p+1][1], qa[2*p+1][2], qa[2*p+1][3], B.z, B.w);
            }
        }

        // ---- softmax in registers (fixed-max; shift-invariant) ----
        if (kb == qb) {
            #pragma unroll
            for (int nt = 0; nt < 8; ++nt) {
                const int c0 = kb * 64 + nt * 8 + lc * 2;
                sf[nt][0] = (c0     <= s0) ? __expf(sf[nt][0]) : 0.0f;
                sf[nt][1] = (c0 + 1 <= s0) ? __expf(sf[nt][1]) : 0.0f;
                sf[nt][2] = (c0     <= s1) ? __expf(sf[nt][2]) : 0.0f;
                sf[nt][3] = (c0 + 1 <= s1) ? __expf(sf[nt][3]) : 0.0f;
                ls0 += sf[nt][0] + sf[nt][1];
                ls1 += sf[nt][2] + sf[nt][3];
            }
        } else {
            #pragma unroll
            for (int nt = 0; nt < 8; ++nt) {
                sf[nt][0] = __expf(sf[nt][0]);
                sf[nt][1] = __expf(sf[nt][1]);
                sf[nt][2] = __expf(sf[nt][2]);
                sf[nt][3] = __expf(sf[nt][3]);
                ls0 += sf[nt][0] + sf[nt][1];
                ls1 += sf[nt][2] + sf[nt][3];
            }
        }

        // ---- O += P V : fp16 m16n8k16; P直接 from C fragments (no shuffles) ----
        const unsigned* Vp = Vb[cur];
        #pragma unroll
        for (int g = 0; g < 2; ++g) {   // g = pair of k16-chunks
            const unsigned aA0 = pack_f16x2(sf[4*g+0][0], sf[4*g+0][1]);
            const unsigned aA1 = pack_f16x2(sf[4*g+0][2], sf[4*g+0][3]);
            const unsigned aA2 = pack_f16x2(sf[4*g+1][0], sf[4*g+1][1]);
            const unsigned aA3 = pack_f16x2(sf[4*g+1][2], sf[4*g+1][3]);
            const unsigned aB0 = pack_f16x2(sf[4*g+2][0], sf[4*g+2][1]);
            const unsigned aB1 = pack_f16x2(sf[4*g+2][2], sf[4*g+2][3]);
            const unsigned aB2 = pack_f16x2(sf[4*g+3][0], sf[4*g+3][1]);
            const unsigned aB3 = pack_f16x2(sf[4*g+3][2], sf[4*g+3][3]);
            #pragma unroll
            for (int nt = 0; nt < 16; ++nt) {
                const uint4 f4 = *(const uint4*)&Vp[(nt * 8 + lr) * VSTR16 + lc * 8 + g * 4];
                mma_f16(oacc[nt], aA0, aA1, aA2, aA3, f4.x, f4.y);   // kc = 2g
                mma_f16(oacc[nt], aB0, aB1, aB2, aB3, f4.z, f4.w);   // kc = 2g+1
            }
        }

        kb = kbn;
        cur ^= 1;
    }

    // ---- epilogue ----
    ls0 += __shfl_xor_sync(0xffffffffu, ls0, 1);
    ls0 += __shfl_xor_sync(0xffffffffu, ls0, 2);
    ls1 += __shfl_xor_sync(0xffffffffu, ls1, 1);
    ls1 += __shfl_xor_sync(0xffffffffu, ls1, 2);
    const float linv0 = 1.0f / ls0;
    const float linv1 = 1.0f / ls1;
    float* O0 = O + ((size_t)s0 * HEADS + h) * DIM;
    float* O1 = O + ((size_t)s1 * HEADS + h) * DIM;
    #pragma unroll
    for (int nt = 0; nt < 16; ++nt) {
        const int col = nt * 8 + lc * 2;
        *(float2*)(O0 + col) = make_float2(oacc[nt][0] * linv0, oacc[nt][1] * linv0);
        *(float2*)(O1 + col) = make_float2(oacc[nt][2] * linv1, oacc[nt][3] * linv1);
    }
}

extern "C" void kernel_launch(void* const* d_in, const int* in_sizes, int n_in,
                              void* d_out, int out_size) {
    const float* Q = (const float*)d_in[0];
    const float* K = (const float*)d_in[1];
    const float* V = (const float*)d_in[2];
    float* O = (float*)d_out;

    const size_t smem = SMEM_WORDS * sizeof(unsigned);   // 77824 B
    static bool attr_set = false;
    if (!attr_set) {
        cudaFuncSetAttribute(sparse_attn_ff_kernel,
                             cudaFuncAttributeMaxDynamicSharedMemorySize, (int)smem);
        attr_set = true;
    }

    prepackK16_kernel<<<4096, 256>>>(K);
    prepackV16_kernel<<<4096, 256>>>(V);
    dim3 grid(32, HEADS);
    sparse_attn_ff_kernel<<<grid, 128, smem>>>(Q, O);
}

// round 12
// speedup vs baseline: 2.5364x; 1.1259x over previous
#include <cuda_runtime.h>
#include <cstdint>

#define HEADS 32
#define S_LEN 2048
#define DIM   128
#define LOCAL 16

#define KSTR   80
#define VSTR16 36
#define KBUF  (64*KSTR)
#define VBUF  (128*VSTR16)
#define SMEM_WORDS (2*KBUF + 2*VBUF)   // 19456 words = 77824 B
#define NJOBS 1024
#define GRID_PERSIST 304

__device__ unsigned g_Kp16[(size_t)HEADS * S_LEN * 64];
__device__ unsigned g_V16 [(size_t)HEADS * 32 * 128 * 32];
__device__ unsigned g_jobCtr;

__device__ __forceinline__ unsigned pack_f16x2(float lo_el, float hi_el) {
    unsigned r; asm("cvt.rn.f16x2.f32 %0, %1, %2;" : "=r"(r) : "f"(hi_el), "f"(lo_el)); return r;
}
__device__ __forceinline__ float fexp2(float x) {
    float y; asm("ex2.approx.ftz.f32 %0, %1;" : "=f"(y) : "f"(x)); return y;
}
__device__ __forceinline__ void mma_f16(float c[4],
                                        unsigned a0, unsigned a1, unsigned a2, unsigned a3,
                                        unsigned b0, unsigned b1) {
    asm volatile(
        "mma.sync.aligned.m16n8k16.row.col.f32.f16.f16.f32 "
        "{%0,%1,%2,%3}, {%4,%5,%6,%7}, {%8,%9}, {%0,%1,%2,%3};"
        : "+f"(c[0]), "+f"(c[1]), "+f"(c[2]), "+f"(c[3])
        : "r"(a0), "r"(a1), "r"(a2), "r"(a3), "r"(b0), "r"(b1));
}
__device__ __forceinline__ uint32_t smem_u32(const void* p) {
    uint32_t a;
    asm("{ .reg .u64 t; cvta.to.shared.u64 t, %1; cvt.u32.u64 %0, t; }" : "=r"(a) : "l"(p));
    return a;
}
__device__ __forceinline__ void cp16(uint32_t dst, const void* src) {
    asm volatile("cp.async.ca.shared.global [%0], [%1], 16;" :: "r"(dst), "l"(src));
}
#define CP_COMMIT() asm volatile("cp.async.commit_group;" ::: "memory")
#define CP_WAIT0()  asm volatile("cp.async.wait_group 0;" ::: "memory")

// ---- merged prepass: K fp16x2 mma-ready + V fp16x2 dim-major permuted + job counter reset ----
__global__ __launch_bounds__(256)
void prepack_all_kernel(const float* __restrict__ K, const float* __restrict__ V) {
    if (blockIdx.x == 0 && threadIdx.x == 0) g_jobCtr = 0u;
    if (blockIdx.x < 4096) {
        const int gid = blockIdx.x * 256 + threadIdx.x;   // 1M: rid x 16
        const int rid = gid >> 4;
        const int j   = gid & 15;
        const int h   = rid >> 11;
        const int s   = rid & 2047;
        const size_t src_row = ((size_t)s * HEADS + h) * DIM;
        unsigned kw[4];
        #pragma unroll
        for (int m = 0; m < 4; ++m) {
            const int i  = 4 * j + m;
            const int p  = i >> 4;
            const int lc = (i >> 2) & 3;
            const int s2 = i & 3;
            const int kg = 2 * p + (s2 >> 1);
            const int d  = kg * 16 + lc * 4 + (s2 & 1) * 2;
            const float2 v = __ldg((const float2*)(K + src_row + d));
            kw[m] = pack_f16x2(v.x, v.y);
        }
        *(uint4*)&g_Kp16[(size_t)rid * 64 + j * 4] = make_uint4(kw[0], kw[1], kw[2], kw[3]);
    } else {
        const int gid = (blockIdx.x - 4096) * 256 + threadIdx.x;   // 1M: rid x 1024
        const int rid = gid >> 10;       // h*32 + kb
        const int t2  = gid & 1023;
        const int d   = t2 & 127;
        const int j   = t2 >> 7;
        const int h   = rid >> 5;
        const int kb  = rid & 31;
        unsigned vw[4];
        #pragma unroll
        for (int m = 0; m < 4; ++m) {
            const int wp = 4 * j + m;
            const int w  = (wp >> 3) + (wp & 7) * 4;
            const int tok = kb * 64 + 2 * w;
            const float a = __ldg(V + ((size_t)tok       * HEADS + h) * DIM + d);
            const float b = __ldg(V + ((size_t)(tok + 1) * HEADS + h) * DIM + d);
            vw[m] = pack_f16x2(a, b);
        }
        *(uint4*)&g_V16[((size_t)rid * 128 + d) * 32 + 4 * j] = make_uint4(vw[0], vw[1], vw[2], vw[3]);
    }
}

__global__ __launch_bounds__(128, 2)
void sparse_attn_pj_kernel(const float* __restrict__ Q,
                           float* __restrict__ O) {
    extern __shared__ unsigned sm[];
    __shared__ unsigned jobSh;
    unsigned* Kb[2] = { sm, sm + KBUF };
    unsigned* Vb[2] = { sm + 2 * KBUF, sm + 2 * KBUF + VBUF };
    const uint32_t sbK[2] = { smem_u32(Kb[0]), smem_u32(Kb[1]) };
    const uint32_t sbV[2] = { smem_u32(Vb[0]), smem_u32(Vb[1]) };

    const int t    = threadIdx.x;   // 0..127
    const int w    = t >> 5;
    const int lane = t & 31;
    const int lr   = lane >> 2;
    const int lc   = lane & 3;
    const float scale2 = 0.12751743f;   // log2(e)/sqrt(128): exp(s) = 2^(s*scale2/scale)

    for (;;) {
        if (t == 0) jobSh = atomicAdd(&g_jobCtr, 1u);
        __syncthreads();                 // also guards smem reuse across jobs
        const unsigned j = jobSh;
        if (j >= NJOBS) break;
        const int qb = 31 - (int)(j >> 5);   // heavy-first (LPT)
        const int h  = (int)(j & 31u);

        const int s0 = qb * 64 + w * 16 + lr;
        const int s1 = s0 + 8;
        const size_t hK = (size_t)h * S_LEN * 64;

        // ---- Q fragments in registers, fp16x2 (scale*log2e folded) ----
        unsigned qa[8][4];
        {
            const float* Qp0 = Q + ((size_t)s0 * HEADS + h) * DIM;
            const float* Qp1 = Q + ((size_t)s1 * HEADS + h) * DIM;
            #pragma unroll
            for (int kg = 0; kg < 8; ++kg) {
                const float4 A = *(const float4*)(Qp0 + kg * 16 + lc * 4);
                const float4 B = *(const float4*)(Qp1 + kg * 16 + lc * 4);
                qa[kg][0] = pack_f16x2(A.x * scale2, A.y * scale2);
                qa[kg][1] = pack_f16x2(B.x * scale2, B.y * scale2);
                qa[kg][2] = pack_f16x2(A.z * scale2, A.w * scale2);
                qa[kg][3] = pack_f16x2(B.z * scale2, B.w * scale2);
            }
        }

        float oacc[16][4];
        #pragma unroll
        for (int nt = 0; nt < 16; ++nt)
            #pragma unroll
            for (int q4 = 0; q4 < 4; ++q4) oacc[nt][q4] = 0.0f;
        float ls0 = 0.0f, ls1 = 0.0f;

        // ---- first allowed kv block; prologue into buffer 0 ----
        int kb = 0;
        while (!(((qb - kb) < LOCAL) || (((kb + h + 1) & 7) == 0))) ++kb;
        {
            const unsigned* gK = g_Kp16 + hK + (size_t)kb * 64 * 64;
            const unsigned* gV = g_V16 + ((size_t)(h * 32 + kb) * 128) * 32;
            #pragma unroll
            for (int it = 0; it < 8; ++it) {
                const int c = t + it * 128;
                const int r = c >> 4, w4 = c & 15;
                cp16(sbK[0] + (r * KSTR + w4 * 4) * 4, gK + r * 64 + w4 * 4);
            }
            #pragma unroll
            for (int it = 0; it < 8; ++it) {
                const int c = t + it * 128;
                const int r = c >> 3, w4 = c & 7;
                cp16(sbV[0] + (r * VSTR16 + w4 * 4) * 4, gV + r * 32 + w4 * 4);
            }
            CP_COMMIT();
        }

        int cur = 0;
        while (kb >= 0) {
            int kbn = kb + 1;
            while (kbn <= qb && !(((qb - kbn) < LOCAL) || (((kbn + h + 1) & 7) == 0))) ++kbn;
            if (kbn > qb) kbn = -1;

            CP_WAIT0();
            __syncthreads();

            if (kbn >= 0) {
                const int nb = cur ^ 1;
                const unsigned* gK = g_Kp16 + hK + (size_t)kbn * 64 * 64;
                const unsigned* gV = g_V16 + ((size_t)(h * 32 + kbn) * 128) * 32;
                #pragma unroll
                for (int it = 0; it < 8; ++it) {
                    const int c = t + it * 128;
                    const int r = c >> 4, w4 = c & 15;
                    cp16(sbK[nb] + (r * KSTR + w4 * 4) * 4, gK + r * 64 + w4 * 4);
                }
                #pragma unroll
                for (int it = 0; it < 8; ++it) {
                    const int c = t + it * 128;
                    const int r = c >> 3, w4 = c & 7;
                    cp16(sbV[nb] + (r * VSTR16 + w4 * 4) * 4, gV + r * 32 + w4 * 4);
                }
                CP_COMMIT();
            }

            const bool diag = (kb == qb);
            const int ntLim = diag ? (2 * w + 2) : 8;   // valid 8-token chunks for this warp

            // ---- S = Q K^T : single-term fp16 (diag: skip fully-masked nt) ----
            const unsigned* Ku = Kb[cur];
            float sf[8][4];
            #pragma unroll
            for (int nt = 0; nt < 8; ++nt)
                #pragma unroll
                for (int q4 = 0; q4 < 4; ++q4) sf[nt][q4] = 0.0f;

            #pragma unroll
            for (int p = 0; p < 4; ++p) {
                #pragma unroll
                for (int nt = 0; nt < 8; ++nt) {
                    if (nt < ntLim) {
                        const uint4 B = *(const uint4*)&Ku[(nt * 8 + lr) * KSTR + p * 16 + lc * 4];
                        mma_f16(sf[nt], qa[2*p][0],   qa[2*p][1],   qa[2*p][2],   qa[2*p][3],   B.x, B.y);
                        mma_f16(sf[nt], qa[2*p+1][0], qa[2*p+1][1], qa[2*p+1][2], qa[2*p+1][3], B.z, B.w);
                    }
                }
            }

            // ---- softmax: p = 2^s (scale*log2e pre-folded); fixed-max (shift-invariant) ----
            if (diag) {
                #pragma unroll
                for (int nt = 0; nt < 8; ++nt) {
                    if (nt < ntLim) {
                        const int c0 = kb * 64 + nt * 8 + lc * 2;
                        sf[nt][0] = (c0     <= s0) ? fexp2(sf[nt][0]) : 0.0f;
                        sf[nt][1] = (c0 + 1 <= s0) ? fexp2(sf[nt][1]) : 0.0f;
                        sf[nt][2] = (c0     <= s1) ? fexp2(sf[nt][2]) : 0.0f;
                        sf[nt][3] = (c0 + 1 <= s1) ? fexp2(sf[nt][3]) : 0.0f;
                        ls0 += sf[nt][0] + sf[nt][1];
                        ls1 += sf[nt][2] + sf[nt][3];
                    }
                }
            } else {
                #pragma unroll
                for (int nt = 0; nt < 8; ++nt) {
                    sf[nt][0] = fexp2(sf[nt][0]);
                    sf[nt][1] = fexp2(sf[nt][1]);
                    sf[nt][2] = fexp2(sf[nt][2]);
                    sf[nt][3] = fexp2(sf[nt][3]);
                    ls0 += sf[nt][0] + sf[nt][1];
                    ls1 += sf[nt][2] + sf[nt][3];
                }
            }

            // ---- O += P V : fp16; P from C fragments directly (diag: skip zero chunk-groups) ----
            const unsigned* Vp = Vb[cur];
            #pragma unroll
            for (int g = 0; g < 2; ++g) {
                const bool doA = (4 * g)     < ntLim;
                const bool doB = (4 * g + 2) < ntLim;
                if (doA || doB) {
                    unsigned aA0, aA1, aA2, aA3, aB0, aB1, aB2, aB3;
                    if (doA) {
                        aA0 = pack_f16x2(sf[4*g+0][0], sf[4*g+0][1]);
                        aA1 = pack_f16x2(sf[4*g+0][2], sf[4*g+0][3]);
                        aA2 = pack_f16x2(sf[4*g+1][0], sf[4*g+1][1]);
                        aA3 = pack_f16x2(sf[4*g+1][2], sf[4*g+1][3]);
                    }
                    if (doB) {
                        aB0 = pack_f16x2(sf[4*g+2][0], sf[4*g+2][1]);
                        aB1 = pack_f16x2(sf[4*g+2][2], sf[4*g+2][3]);
                        aB2 = pack_f16x2(sf[4*g+3][0], sf[4*g+3][1]);
                        aB3 = pack_f16x2(sf[4*g+3][2], sf[4*g+3][3]);
                    }
                    #pragma unroll
                    for (int nt = 0; nt < 16; ++nt) {
                        const uint4 f4 = *(const uint4*)&Vp[(nt * 8 + lr) * VSTR16 + lc * 8 + g * 4];
                        if (doA) mma_f16(oacc[nt], aA0, aA1, aA2, aA3, f4.x, f4.y);
                        if (doB) mma_f16(oacc[nt], aB0, aB1, aB2, aB3, f4.z, f4.w);
                    }
                }
            }

            kb = kbn;
            cur ^= 1;
        }

        // ---- epilogue ----
        ls0 += __shfl_xor_sync(0xffffffffu, ls0, 1);
        ls0 += __shfl_xor_sync(0xffffffffu, ls0, 2);
        ls1 += __shfl_xor_sync(0xffffffffu, ls1, 1);
        ls1 += __shfl_xor_sync(0xffffffffu, ls1, 2);
        const float linv0 = 1.0f / ls0;
        const float linv1 = 1.0f / ls1;
        float* O0 = O + ((size_t)s0 * HEADS + h) * DIM;
        float* O1 = O + ((size_t)s1 * HEADS + h) * DIM;
        #pragma unroll
        for (int nt = 0; nt < 16; ++nt) {
            const int col = nt * 8 + lc * 2;
            *(float2*)(O0 + col) = make_float2(oacc[nt][0] * linv0, oacc[nt][1] * linv0);
            *(float2*)(O1 + col) = make_float2(oacc[nt][2] * linv1, oacc[nt][3] * linv1);
        }
    }
}

extern "C" void kernel_launch(void* const* d_in, const int* in_sizes, int n_in,
                              void* d_out, int out_size) {
    const float* Q = (const float*)d_in[0];
    const float* K = (const float*)d_in[1];
    const float* V = (const float*)d_in[2];
    float* O = (float*)d_out;

    const size_t smem = SMEM_WORDS * sizeof(unsigned);   // 77824 B
    static bool attr_set = false;
    if (!attr_set) {
        cudaFuncSetAttribute(sparse_attn_pj_kernel,
                             cudaFuncAttributeMaxDynamicSharedMemorySize, (int)smem);
        attr_set = true;
    }

    prepack_all_kernel<<<8192, 256>>>(K, V);          // also resets g_jobCtr
    sparse_attn_pj_kernel<<<GRID_PERSIST, 128, smem>>>(Q, O);
}

// round 13
// speedup vs baseline: 2.6461x; 1.0432x over previous
#include <cuda_runtime.h>
#include <cstdint>

#define HEADS 32
#define S_LEN 2048
#define DIM   128
#define LOCAL 16

#define KSTR   80
#define VSTR16 36
#define KBUF  (64*KSTR)        // 5120 words
#define VBUF  (128*VSTR16)     // 4608 words
#define SMEM_WORDS (2*KBUF + VBUF)   // 14848 words = 59392 B
#define NJOBS 1024
#define GRID_PERSIST 444

__device__ unsigned g_Kp16[(size_t)HEADS * S_LEN * 64];
__device__ unsigned g_V16 [(size_t)HEADS * 32 * 128 * 32];
__device__ unsigned g_jobCtr;

__device__ __forceinline__ unsigned pack_f16x2(float lo_el, float hi_el) {
    unsigned r; asm("cvt.rn.f16x2.f32 %0, %1, %2;" : "=r"(r) : "f"(hi_el), "f"(lo_el)); return r;
}
__device__ __forceinline__ float fexp2(float x) {
    float y; asm("ex2.approx.ftz.f32 %0, %1;" : "=f"(y) : "f"(x)); return y;
}
__device__ __forceinline__ void mma_f16(float c[4],
                                        unsigned a0, unsigned a1, unsigned a2, unsigned a3,
                                        unsigned b0, unsigned b1) {
    asm volatile(
        "mma.sync.aligned.m16n8k16.row.col.f32.f16.f16.f32 "
        "{%0,%1,%2,%3}, {%4,%5,%6,%7}, {%8,%9}, {%0,%1,%2,%3};"
        : "+f"(c[0]), "+f"(c[1]), "+f"(c[2]), "+f"(c[3])
        : "r"(a0), "r"(a1), "r"(a2), "r"(a3), "r"(b0), "r"(b1));
}
__device__ __forceinline__ uint32_t smem_u32(const void* p) {
    uint32_t a;
    asm("{ .reg .u64 t; cvta.to.shared.u64 t, %1; cvt.u32.u64 %0, t; }" : "=r"(a) : "l"(p));
    return a;
}
__device__ __forceinline__ void cp16(uint32_t dst, const void* src) {
    asm volatile("cp.async.ca.shared.global [%0], [%1], 16;" :: "r"(dst), "l"(src));
}
#define CP_COMMIT() asm volatile("cp.async.commit_group;" ::: "memory")
#define CP_WAIT(N)  asm volatile("cp.async.wait_group %0;" :: "n"(N) : "memory")

// ---- merged prepass: K fp16x2 mma-ready + V fp16x2 dim-major permuted + counter reset ----
__global__ __launch_bounds__(256)
void prepack_all_kernel(const float* __restrict__ K, const float* __restrict__ V) {
    if (blockIdx.x == 0 && threadIdx.x == 0) g_jobCtr = 0u;
    if (blockIdx.x < 4096) {
        const int gid = blockIdx.x * 256 + threadIdx.x;
        const int rid = gid >> 4;
        const int j   = gid & 15;
        const int h   = rid >> 11;
        const int s   = rid & 2047;
        const size_t src_row = ((size_t)s * HEADS + h) * DIM;
        unsigned kw[4];
        #pragma unroll
        for (int m = 0; m < 4; ++m) {
            const int i  = 4 * j + m;
            const int p  = i >> 4;
            const int lc = (i >> 2) & 3;
            const int s2 = i & 3;
            const int kg = 2 * p + (s2 >> 1);
            const int d  = kg * 16 + lc * 4 + (s2 & 1) * 2;
            const float2 v = __ldg((const float2*)(K + src_row + d));
            kw[m] = pack_f16x2(v.x, v.y);
        }
        *(uint4*)&g_Kp16[(size_t)rid * 64 + j * 4] = make_uint4(kw[0], kw[1], kw[2], kw[3]);
    } else {
        const int gid = (blockIdx.x - 4096) * 256 + threadIdx.x;
        const int rid = gid >> 10;       // h*32 + kb
        const int t2  = gid & 1023;
        const int d   = t2 & 127;
        const int j   = t2 >> 7;
        const int h   = rid >> 5;
        const int kb  = rid & 31;
        unsigned vw[4];
        #pragma unroll
        for (int m = 0; m < 4; ++m) {
            const int wp = 4 * j + m;
            const int w  = (wp >> 3) + (wp & 7) * 4;
            const int tok = kb * 64 + 2 * w;
            const float a = __ldg(V + ((size_t)tok       * HEADS + h) * DIM + d);
            const float b = __ldg(V + ((size_t)(tok + 1) * HEADS + h) * DIM + d);
            vw[m] = pack_f16x2(a, b);
        }
        *(uint4*)&g_V16[((size_t)rid * 128 + d) * 32 + 4 * j] = make_uint4(vw[0], vw[1], vw[2], vw[3]);
    }
}

__global__ __launch_bounds__(128, 3)
void sparse_attn_o3_kernel(const float* __restrict__ Q,
                           float* __restrict__ O) {
    extern __shared__ unsigned sm[];
    __shared__ unsigned jobSh;
    const uint32_t sbK0 = smem_u32(sm);
    const uint32_t sbK1 = sbK0 + KBUF * 4;
    const uint32_t sbV  = sbK0 + 2 * KBUF * 4;
    unsigned* Vb = sm + 2 * KBUF;

    const int t    = threadIdx.x;   // 0..127
    const int w    = t >> 5;
    const int lane = t & 31;
    const int lr   = lane >> 2;
    const int lc   = lane & 3;
    const float scale2 = 0.12751743f;   // log2(e)/sqrt(128)

    for (;;) {
        if (t == 0) jobSh = atomicAdd(&g_jobCtr, 1u);
        __syncthreads();
        const unsigned j = jobSh;
        if (j >= NJOBS) break;
        const int qb = 31 - (int)(j >> 5);   // heavy-first (LPT)
        const int h  = (int)(j & 31u);

        const int s0 = qb * 64 + w * 16 + lr;
        const int s1 = s0 + 8;
        const size_t hK = (size_t)h * S_LEN * 64;

        // ---- Q fragments (scale*log2e folded) ----
        unsigned qa[8][4];
        {
            const float* Qp0 = Q + ((size_t)s0 * HEADS + h) * DIM;
            const float* Qp1 = Q + ((size_t)s1 * HEADS + h) * DIM;
            #pragma unroll
            for (int kg = 0; kg < 8; ++kg) {
                const float4 A = *(const float4*)(Qp0 + kg * 16 + lc * 4);
                const float4 B = *(const float4*)(Qp1 + kg * 16 + lc * 4);
                qa[kg][0] = pack_f16x2(A.x * scale2, A.y * scale2);
                qa[kg][1] = pack_f16x2(B.x * scale2, B.y * scale2);
                qa[kg][2] = pack_f16x2(A.z * scale2, A.w * scale2);
                qa[kg][3] = pack_f16x2(B.z * scale2, B.w * scale2);
            }
        }

        float oacc[16][4];
        #pragma unroll
        for (int nt = 0; nt < 16; ++nt)
            #pragma unroll
            for (int q4 = 0; q4 < 4; ++q4) oacc[nt][q4] = 0.0f;
        float ls0 = 0.0f, ls1 = 0.0f;

        // ---- first allowed kv block; K prologue into buffer 0 ----
        int kb = 0;
        while (!(((qb - kb) < LOCAL) || (((kb + h + 1) & 7) == 0))) ++kb;
        {
            const unsigned* gK = g_Kp16 + hK + (size_t)kb * 64 * 64;
            #pragma unroll
            for (int it = 0; it < 8; ++it) {
                const int c = t + it * 128;
                const int r = c >> 4, w4 = c & 15;
                cp16(sbK0 + (r * KSTR + w4 * 4) * 4, gK + r * 64 + w4 * 4);
            }
            CP_COMMIT();
        }

        int cur = 0;
        while (kb >= 0) {
            int kbn = kb + 1;
            while (kbn <= qb && !(((qb - kbn) < LOCAL) || (((kbn + h + 1) & 7) == 0))) ++kbn;
            if (kbn > qb) kbn = -1;

            CP_WAIT(0);          // K(cur) resident
            __syncthreads();     // visible; V buffer free (prev PV done by all warps)

            // ---- issue V(kb), then K(kbn): both overlap QK+softmax ----
            {
                const unsigned* gV = g_V16 + ((size_t)(h * 32 + kb) * 128) * 32;
                #pragma unroll
                for (int it = 0; it < 8; ++it) {
                    const int c = t + it * 128;
                    const int r = c >> 3, w4 = c & 7;
                    cp16(sbV + (r * VSTR16 + w4 * 4) * 4, gV + r * 32 + w4 * 4);
                }
                CP_COMMIT();     // group: V
            }
            if (kbn >= 0) {
                const uint32_t dstK = cur ? sbK0 : sbK1;
                const unsigned* gK = g_Kp16 + hK + (size_t)kbn * 64 * 64;
                #pragma unroll
                for (int it = 0; it < 8; ++it) {
                    const int c = t + it * 128;
                    const int r = c >> 4, w4 = c & 15;
                    cp16(dstK + (r * KSTR + w4 * 4) * 4, gK + r * 64 + w4 * 4);
                }
                CP_COMMIT();     // group: K(next)
            }

            const bool diag = (kb == qb);
            const int ntLim = diag ? (2 * w + 2) : 8;

            // ---- S = Q K^T : fp16 m16n8k16 (diag: skip fully-masked nt) ----
            const unsigned* Ku = sm + cur * KBUF;
            float sf[8][4];
            #pragma unroll
            for (int nt = 0; nt < 8; ++nt)
                #pragma unroll
                for (int q4 = 0; q4 < 4; ++q4) sf[nt][q4] = 0.0f;

            #pragma unroll
            for (int p = 0; p < 4; ++p) {
                #pragma unroll
                for (int nt = 0; nt < 8; ++nt) {
                    if (nt < ntLim) {
                        const uint4 B = *(const uint4*)&Ku[(nt * 8 + lr) * KSTR + p * 16 + lc * 4];
                        mma_f16(sf[nt], qa[2*p][0],   qa[2*p][1],   qa[2*p][2],   qa[2*p][3],   B.x, B.y);
                        mma_f16(sf[nt], qa[2*p+1][0], qa[2*p+1][1], qa[2*p+1][2], qa[2*p+1][3], B.z, B.w);
                    }
                }
            }

            // ---- softmax: p = 2^s; fixed-max (shift-invariant) ----
            if (diag) {
                #pragma unroll
                for (int nt = 0; nt < 8; ++nt) {
                    if (nt < ntLim) {
                        const int c0 = kb * 64 + nt * 8 + lc * 2;
                        sf[nt][0] = (c0     <= s0) ? fexp2(sf[nt][0]) : 0.0f;
                        sf[nt][1] = (c0 + 1 <= s0) ? fexp2(sf[nt][1]) : 0.0f;
                        sf[nt][2] = (c0     <= s1) ? fexp2(sf[nt][2]) : 0.0f;
                        sf[nt][3] = (c0 + 1 <= s1) ? fexp2(sf[nt][3]) : 0.0f;
                        ls0 += sf[nt][0] + sf[nt][1];
                        ls1 += sf[nt][2] + sf[nt][3];
                    }
                }
            } else {
                #pragma unroll
                for (int nt = 0; nt < 8; ++nt) {
                    sf[nt][0] = fexp2(sf[nt][0]);
                    sf[nt][1] = fexp2(sf[nt][1]);
                    sf[nt][2] = fexp2(sf[nt][2]);
                    sf[nt][3] = fexp2(sf[nt][3]);
                    ls0 += sf[nt][0] + sf[nt][1];
                    ls1 += sf[nt][2] + sf[nt][3];
                }
            }

            // ---- wait V (K-next may stay pending), sync, PV ----
            if (kbn >= 0) { CP_WAIT(1); } else { CP_WAIT(0); }
            __syncthreads();

            #pragma unroll
            for (int g = 0; g < 2; ++g) {
                const bool doA = (4 * g)     < ntLim;
                const bool doB = (4 * g + 2) < ntLim;
                if (doA || doB) {
                    unsigned aA0, aA1, aA2, aA3, aB0, aB1, aB2, aB3;
                    if (doA) {
                        aA0 = pack_f16x2(sf[4*g+0][0], sf[4*g+0][1]);
                        aA1 = pack_f16x2(sf[4*g+0][2], sf[4*g+0][3]);
                        aA2 = pack_f16x2(sf[4*g+1][0], sf[4*g+1][1]);
                        aA3 = pack_f16x2(sf[4*g+1][2], sf[4*g+1][3]);
                    }
                    if (doB) {
                        aB0 = pack_f16x2(sf[4*g+2][0], sf[4*g+2][1]);
                        aB1 = pack_f16x2(sf[4*g+2][2], sf[4*g+2][3]);
                        aB2 = pack_f16x2(sf[4*g+3][0], sf[4*g+3][1]);
                        aB3 = pack_f16x2(sf[4*g+3][2], sf[4*g+3][3]);
                    }
                    #pragma unroll
                    for (int nt = 0; nt < 16; ++nt) {
                        const uint4 f4 = *(const uint4*)&Vb[(nt * 8 + lr) * VSTR16 + lc * 8 + g * 4];
                        if (doA) mma_f16(oacc[nt], aA0, aA1, aA2, aA3, f4.x, f4.y);
                        if (doB) mma_f16(oacc[nt], aB0, aB1, aB2, aB3, f4.z, f4.w);
                    }
                }
            }

            kb = kbn;
            cur ^= 1;
        }

        // ---- epilogue ----
        ls0 += __shfl_xor_sync(0xffffffffu, ls0, 1);
        ls0 += __shfl_xor_sync(0xffffffffu, ls0, 2);
        ls1 += __shfl_xor_sync(0xffffffffu, ls1, 1);
        ls1 += __shfl_xor_sync(0xffffffffu, ls1, 2);
        const float linv0 = 1.0f / ls0;
        const float linv1 = 1.0f / ls1;
        float* O0 = O + ((size_t)s0 * HEADS + h) * DIM;
        float* O1 = O + ((size_t)s1 * HEADS + h) * DIM;
        #pragma unroll
        for (int nt = 0; nt < 16; ++nt) {
            const int col = nt * 8 + lc * 2;
            *(float2*)(O0 + col) = make_float2(oacc[nt][0] * linv0, oacc[nt][1] * linv0);
            *(float2*)(O1 + col) = make_float2(oacc[nt][2] * linv1, oacc[nt][3] * linv1);
        }
    }
}

extern "C" void kernel_launch(void* const* d_in, const int* in_sizes, int n_in,
                              void* d_out, int out_size) {
    const float* Q = (const float*)d_in[0];
    const float* K = (const float*)d_in[1];
    const float* V = (const float*)d_in[2];
    float* O = (float*)d_out;

    const size_t smem = SMEM_WORDS * sizeof(unsigned);   // 59392 B
    static bool attr_set = false;
    if (!attr_set) {
        cudaFuncSetAttribute(sparse_attn_o3_kernel,
                             cudaFuncAttributeMaxDynamicSharedMemorySize, (int)smem);
        attr_set = true;
    }

    prepack_all_kernel<<<8192, 256>>>(K, V);          // also resets g_jobCtr
    sparse_attn_o3_kernel<<<GRID_PERSIST, 128, smem>>>(Q, O);
}

// round 14
// speedup vs baseline: 2.7119x; 1.0249x over previous
#include <cuda_runtime.h>
#include <cstdint>

#define HEADS 32
#define S_LEN 2048
#define DIM   128
#define LOCAL 16

#define KSTR 64                 // words per K row, XOR-swizzled (chunk ^ (row&1)<<2)
#define VSTR 32                 // words per V dim-row, XOR-swizzled (chunk ^ row&1)
#define KBUF (64*KSTR)          // 4096 words
#define VBUF (128*VSTR)         // 4096 words
#define SMEM_WORDS (2*KBUF + 2*VBUF)   // 16384 words = 65536 B
#define NJOBS 1024
#define GRID_PERSIST 444

__device__ unsigned g_Kp16[(size_t)HEADS * S_LEN * 64];
__device__ unsigned g_V16 [(size_t)HEADS * 32 * 128 * 32];
__device__ unsigned g_jobCtr;

__device__ __forceinline__ unsigned pack_f16x2(float lo_el, float hi_el) {
    unsigned r; asm("cvt.rn.f16x2.f32 %0, %1, %2;" : "=r"(r) : "f"(hi_el), "f"(lo_el)); return r;
}
__device__ __forceinline__ float fexp2(float x) {
    float y; asm("ex2.approx.ftz.f32 %0, %1;" : "=f"(y) : "f"(x)); return y;
}
__device__ __forceinline__ void mma_f16(float c[4],
                                        unsigned a0, unsigned a1, unsigned a2, unsigned a3,
                                        unsigned b0, unsigned b1) {
    asm volatile(
        "mma.sync.aligned.m16n8k16.row.col.f32.f16.f16.f32 "
        "{%0,%1,%2,%3}, {%4,%5,%6,%7}, {%8,%9}, {%0,%1,%2,%3};"
        : "+f"(c[0]), "+f"(c[1]), "+f"(c[2]), "+f"(c[3])
        : "r"(a0), "r"(a1), "r"(a2), "r"(a3), "r"(b0), "r"(b1));
}
__device__ __forceinline__ uint32_t smem_u32(const void* p) {
    uint32_t a;
    asm("{ .reg .u64 t; cvta.to.shared.u64 t, %1; cvt.u32.u64 %0, t; }" : "=r"(a) : "l"(p));
    return a;
}
__device__ __forceinline__ void cp16(uint32_t dst, const void* src) {
    asm volatile("cp.async.ca.shared.global [%0], [%1], 16;" :: "r"(dst), "l"(src));
}
#define CP_COMMIT() asm volatile("cp.async.commit_group;" ::: "memory")
#define CP_WAIT0()  asm volatile("cp.async.wait_group 0;" ::: "memory")

// ---- merged prepass: K fp16x2 mma-ready + V fp16x2 dim-major permuted + counter reset ----
__global__ __launch_bounds__(256)
void prepack_all_kernel(const float* __restrict__ K, const float* __restrict__ V) {
    if (blockIdx.x == 0 && threadIdx.x == 0) g_jobCtr = 0u;
    if (blockIdx.x < 4096) {
        const int gid = blockIdx.x * 256 + threadIdx.x;
        const int rid = gid >> 4;
        const int j   = gid & 15;
        const int h   = rid >> 11;
        const int s   = rid & 2047;
        const size_t src_row = ((size_t)s * HEADS + h) * DIM;
        unsigned kw[4];
        #pragma unroll
        for (int m = 0; m < 4; ++m) {
            const int i  = 4 * j + m;
            const int p  = i >> 4;
            const int lc = (i >> 2) & 3;
            const int s2 = i & 3;
            const int kg = 2 * p + (s2 >> 1);
            const int d  = kg * 16 + lc * 4 + (s2 & 1) * 2;
            const float2 v = __ldg((const float2*)(K + src_row + d));
            kw[m] = pack_f16x2(v.x, v.y);
        }
        *(uint4*)&g_Kp16[(size_t)rid * 64 + j * 4] = make_uint4(kw[0], kw[1], kw[2], kw[3]);
    } else {
        const int gid = (blockIdx.x - 4096) * 256 + threadIdx.x;
        const int rid = gid >> 10;       // h*32 + kb
        const int t2  = gid & 1023;
        const int d   = t2 & 127;
        const int j   = t2 >> 7;
        const int h   = rid >> 5;
        const int kb  = rid & 31;
        unsigned vw[4];
        #pragma unroll
        for (int m = 0; m < 4; ++m) {
            const int wp = 4 * j + m;
            const int w  = (wp >> 3) + (wp & 7) * 4;
            const int tok = kb * 64 + 2 * w;
            const float a = __ldg(V + ((size_t)tok       * HEADS + h) * DIM + d);
            const float b = __ldg(V + ((size_t)(tok + 1) * HEADS + h) * DIM + d);
            vw[m] = pack_f16x2(a, b);
        }
        *(uint4*)&g_V16[((size_t)rid * 128 + d) * 32 + 4 * j] = make_uint4(vw[0], vw[1], vw[2], vw[3]);
    }
}

__global__ __launch_bounds__(128, 3)
void sparse_attn_sw_kernel(const float* __restrict__ Q,
                           float* __restrict__ O) {
    extern __shared__ unsigned sm[];
    __shared__ unsigned jobSh;
    const uint32_t sbBase = smem_u32(sm);

    const int t    = threadIdx.x;   // 0..127
    const int w    = t >> 5;
    const int lane = t & 31;
    const int lr   = lane >> 2;
    const int lc   = lane & 3;
    const int kx   = (lr & 1) << 2;   // K swizzle term
    const int vx   = lr & 1;          // V swizzle term
    const float scale2 = 0.12751743f; // log2(e)/sqrt(128)

    // per-thread copy-loop constants
    // K: c = t + it*128 -> r = c>>4, w4 = c&15; swizzled chunk = w4 ^ ((r&1)<<2)
    // V: c = t + it*128 -> r = c>>3, w4 = c&7;  swizzled chunk = w4 ^ (r&1)

    for (;;) {
        if (t == 0) jobSh = atomicAdd(&g_jobCtr, 1u);
        __syncthreads();                  // also: all warps done with smem of prior job
        const unsigned j = jobSh;
        if (j >= NJOBS) break;
        const int qb = 31 - (int)(j >> 5);    // heavy-first (LPT)
        const int h  = (int)(j & 31u);

        const int s0 = qb * 64 + w * 16 + lr;
        const int s1 = s0 + 8;
        const size_t hK = (size_t)h * S_LEN * 64;

        // ---- Q fragments (scale*log2e folded) ----
        unsigned qa[8][4];
        {
            const float* Qp0 = Q + ((size_t)s0 * HEADS + h) * DIM;
            const float* Qp1 = Q + ((size_t)s1 * HEADS + h) * DIM;
            #pragma unroll
            for (int kg = 0; kg < 8; ++kg) {
                const float4 A = *(const float4*)(Qp0 + kg * 16 + lc * 4);
                const float4 B = *(const float4*)(Qp1 + kg * 16 + lc * 4);
                qa[kg][0] = pack_f16x2(A.x * scale2, A.y * scale2);
                qa[kg][1] = pack_f16x2(B.x * scale2, B.y * scale2);
                qa[kg][2] = pack_f16x2(A.z * scale2, A.w * scale2);
                qa[kg][3] = pack_f16x2(B.z * scale2, B.w * scale2);
            }
        }

        float oacc[16][4];
        #pragma unroll
        for (int nt = 0; nt < 16; ++nt)
            #pragma unroll
            for (int q4 = 0; q4 < 4; ++q4) oacc[nt][q4] = 0.0f;
        float ls0 = 0.0f, ls1 = 0.0f;

        // ---- first allowed kv block; prologue K+V into buffer 0 ----
        int kb = 0;
        while (!(((qb - kb) < LOCAL) || (((kb + h + 1) & 7) == 0))) ++kb;
        {
            const unsigned* gK = g_Kp16 + hK + (size_t)kb * 64 * 64;
            const unsigned* gV = g_V16 + ((size_t)(h * 32 + kb) * 128) * 32;
            #pragma unroll
            for (int it = 0; it < 8; ++it) {
                const int c = t + it * 128;
                const int r = c >> 4, w4 = c & 15;
                cp16(sbBase + (r * 64 + (w4 ^ ((r & 1) << 2)) * 4) * 4, gK + r * 64 + w4 * 4);
            }
            #pragma unroll
            for (int it = 0; it < 8; ++it) {
                const int c = t + it * 128;
                const int r = c >> 3, w4 = c & 7;
                cp16(sbBase + (2 * KBUF + r * 32 + (w4 ^ (r & 1)) * 4) * 4, gV + r * 32 + w4 * 4);
            }
            CP_COMMIT();
        }

        int cur = 0;
        while (kb >= 0) {
            int kbn = kb + 1;
            while (kbn <= qb && !(((qb - kbn) < LOCAL) || (((kbn + h + 1) & 7) == 0))) ++kbn;
            if (kbn > qb) kbn = -1;

            CP_WAIT0();          // K(kb)+V(kb) resident (issued a full phase ago)
            __syncthreads();     // visible to all; other buffer free

            // ---- issue K(kbn)+V(kbn) into the other buffer (overlaps full compute) ----
            if (kbn >= 0) {
                const int nb = cur ^ 1;
                const unsigned* gK = g_Kp16 + hK + (size_t)kbn * 64 * 64;
                const unsigned* gV = g_V16 + ((size_t)(h * 32 + kbn) * 128) * 32;
                const uint32_t dK = sbBase + nb * KBUF * 4;
                const uint32_t dV = sbBase + (2 * KBUF + nb * VBUF) * 4;
                #pragma unroll
                for (int it = 0; it < 8; ++it) {
                    const int c = t + it * 128;
                    const int r = c >> 4, w4 = c & 15;
                    cp16(dK + (r * 64 + (w4 ^ ((r & 1) << 2)) * 4) * 4, gK + r * 64 + w4 * 4);
                }
                #pragma unroll
                for (int it = 0; it < 8; ++it) {
                    const int c = t + it * 128;
                    const int r = c >> 3, w4 = c & 7;
                    cp16(dV + (r * 32 + (w4 ^ (r & 1)) * 4) * 4, gV + r * 32 + w4 * 4);
                }
                CP_COMMIT();
            }

            const bool diag = (kb == qb);
            const int ntLim = diag ? (2 * w + 2) : 8;

            // ---- S = Q K^T : fp16 m16n8k16 (swizzled K reads) ----
            const unsigned* Ku = sm + cur * KBUF;
            float sf[8][4];
            #pragma unroll
            for (int nt = 0; nt < 8; ++nt)
                #pragma unroll
                for (int q4 = 0; q4 < 4; ++q4) sf[nt][q4] = 0.0f;

            #pragma unroll
            for (int p = 0; p < 4; ++p) {
                #pragma unroll
                for (int nt = 0; nt < 8; ++nt) {
                    if (nt < ntLim) {
                        const uint4 B = *(const uint4*)&Ku[(nt * 8 + lr) * 64 + ((p * 4 + lc) ^ kx) * 4];
                        mma_f16(sf[nt], qa[2*p][0],   qa[2*p][1],   qa[2*p][2],   qa[2*p][3],   B.x, B.y);
                        mma_f16(sf[nt], qa[2*p+1][0], qa[2*p+1][1], qa[2*p+1][2], qa[2*p+1][3], B.z, B.w);
                    }
                }
            }

            // ---- softmax: p = 2^s; fixed-max (shift-invariant) ----
            if (diag) {
                #pragma unroll
                for (int nt = 0; nt < 8; ++nt) {
                    if (nt < ntLim) {
                        const int c0 = kb * 64 + nt * 8 + lc * 2;
                        sf[nt][0] = (c0     <= s0) ? fexp2(sf[nt][0]) : 0.0f;
                        sf[nt][1] = (c0 + 1 <= s0) ? fexp2(sf[nt][1]) : 0.0f;
                        sf[nt][2] = (c0     <= s1) ? fexp2(sf[nt][2]) : 0.0f;
                        sf[nt][3] = (c0 + 1 <= s1) ? fexp2(sf[nt][3]) : 0.0f;
                        ls0 += sf[nt][0] + sf[nt][1];
                        ls1 += sf[nt][2] + sf[nt][3];
                    }
                }
            } else {
                #pragma unroll
                for (int nt = 0; nt < 8; ++nt) {
                    sf[nt][0] = fexp2(sf[nt][0]);
                    sf[nt][1] = fexp2(sf[nt][1]);
                    sf[nt][2] = fexp2(sf[nt][2]);
                    sf[nt][3] = fexp2(sf[nt][3]);
                    ls0 += sf[nt][0] + sf[nt][1];
                    ls1 += sf[nt][2] + sf[nt][3];
                }
            }

            // ---- O += P V : fp16; P from C fragments directly (V already resident) ----
            const unsigned* Vp = sm + 2 * KBUF + cur * VBUF;
            #pragma unroll
            for (int g = 0; g < 2; ++g) {
                const bool doA = (4 * g)     < ntLim;
                const bool doB = (4 * g + 2) < ntLim;
                if (doA || doB) {
                    unsigned aA0, aA1, aA2, aA3, aB0, aB1, aB2, aB3;
                    if (doA) {
                        aA0 = pack_f16x2(sf[4*g+0][0], sf[4*g+0][1]);
                        aA1 = pack_f16x2(sf[4*g+0][2], sf[4*g+0][3]);
                        aA2 = pack_f16x2(sf[4*g+1][0], sf[4*g+1][1]);
                        aA3 = pack_f16x2(sf[4*g+1][2], sf[4*g+1][3]);
                    }
                    if (doB) {
                        aB0 = pack_f16x2(sf[4*g+2][0], sf[4*g+2][1]);
                        aB1 = pack_f16x2(sf[4*g+2][2], sf[4*g+2][3]);
                        aB2 = pack_f16x2(sf[4*g+3][0], sf[4*g+3][1]);
                        aB3 = pack_f16x2(sf[4*g+3][2], sf[4*g+3][3]);
                    }
                    #pragma unroll
                    for (int nt = 0; nt < 16; ++nt) {
                        const uint4 f4 = *(const uint4*)&Vp[(nt * 8 + lr) * 32 + ((2 * lc + g) ^ vx) * 4];
                        if (doA) mma_f16(oacc[nt], aA0, aA1, aA2, aA3, f4.x, f4.y);
                        if (doB) mma_f16(oacc[nt], aB0, aB1, aB2, aB3, f4.z, f4.w);
                    }
                }
            }

            kb = kbn;
            cur ^= 1;
        }

        // ---- epilogue ----
        ls0 += __shfl_xor_sync(0xffffffffu, ls0, 1);
        ls0 += __shfl_xor_sync(0xffffffffu, ls0, 2);
        ls1 += __shfl_xor_sync(0xffffffffu, ls1, 1);
        ls1 += __shfl_xor_sync(0xffffffffu, ls1, 2);
        const float linv0 = 1.0f / ls0;
        const float linv1 = 1.0f / ls1;
        float* O0 = O + ((size_t)s0 * HEADS + h) * DIM;
        float* O1 = O + ((size_t)s1 * HEADS + h) * DIM;
        #pragma unroll
        for (int nt = 0; nt < 16; ++nt) {
            const int col = nt * 8 + lc * 2;
            *(float2*)(O0 + col) = make_float2(oacc[nt][0] * linv0, oacc[nt][1] * linv0);
            *(float2*)(O1 + col) = make_float2(oacc[nt][2] * linv1, oacc[nt][3] * linv1);
        }
    }
}

extern "C" void kernel_launch(void* const* d_in, const int* in_sizes, int n_in,
                              void* d_out, int out_size) {
    const float* Q = (const float*)d_in[0];
    const float* K = (const float*)d_in[1];
    const float* V = (const float*)d_in[2];
    float* O = (float*)d_out;

    const size_t smem = SMEM_WORDS * sizeof(unsigned);   // 65536 B
    static bool attr_set = false;
    if (!attr_set) {
        cudaFuncSetAttribute(sparse_attn_sw_kernel,
                             cudaFuncAttributeMaxDynamicSharedMemorySize, (int)smem);
        attr_set = true;
    }

    prepack_all_kernel<<<8192, 256>>>(K, V);          // also resets g_jobCtr
    sparse_attn_sw_kernel<<<GRID_PERSIST, 128, smem>>>(Q, O);
}